// round 11
// baseline (speedup 1.0000x reference)
#include <cuda_runtime.h>
#include <cstdint>

// Problem dims
#define BB 32
#define SS 64
#define TT 48
#define TM 47      // T-1 decoder steps
#define VV 32000
#define EE 512
#define HH 1024
#define H3 3072
#define H2 2048
#define KSPLIT 4
#define PARTSZ ((size_t)BB * H3)

// ---------------- scratch (device global, no allocs) ----------------
#define OFF_EMBS   0ull                                   // [b][s][e]
#define OFF_GI0    (OFF_EMBS   + (size_t)BB*SS*EE)        // [t][b][n]
#define OFF_ENCOUT (OFF_GI0    + (size_t)BB*SS*H3)        // [b][t][h]
#define OFF_PROJ   (OFF_ENCOUT + (size_t)BB*SS*HH)        // [b][s][h]
#define OFF_ENCV   (OFF_PROJ   + (size_t)BB*SS*HH)        // [b][s][n]  encout @ Wc^T
#define OFF_EMBT   (OFF_ENCV   + (size_t)BB*SS*H3)        // rows m=t*B+b
#define OFF_EPRE   (OFF_EMBT   + (size_t)TM*BB*EE)        // [t][b][n]
#define OFF_CAT    (OFF_EPRE   + (size_t)TM*BB*H3)        // rows m=t*B+b, [d1|ctx]
#define OFF_H0A    (OFF_CAT    + (size_t)TM*BB*H2)        // state [b][h] row-major
#define OFF_H0B    (OFF_H0A    + (size_t)BB*HH)
#define OFF_H1A    (OFF_H0B    + (size_t)BB*HH)
#define OFF_H1B    (OFF_H1A    + (size_t)BB*HH)
#define OFF_ATTW   (OFF_H1B    + (size_t)BB*HH)           // attn weights [b][64]
#define OFF_PART   (OFF_ATTW   + (size_t)BB*SS)           // 12 partial slabs [b][n]
#define OFF_WT     (OFF_PART   + 12*PARTSZ)               // 6 transposed weights [k][n]
#define WT_SZ      ((size_t)HH * H3)
#define SCRATCH_TOTAL (OFF_WT + 6*WT_SZ)

__device__ float g_scratch[SCRATCH_TOTAL];

// ---------------- small helpers ----------------
__device__ __forceinline__ float4 ld4(const float* p) {
    return *reinterpret_cast<const float4*>(p);
}
__device__ __forceinline__ void st4(float* p, float4 v) {
    *reinterpret_cast<float4*>(p) = v;
}

__global__ void zero_kernel(float* p, int n) {
    int i = blockIdx.x * blockDim.x + threadIdx.x;
    if (i < n) p[i] = 0.f;
}

__global__ void embed_enc_kernel(const int* __restrict__ ids,
                                 const float* __restrict__ table,
                                 float* __restrict__ out) {
    int i = blockIdx.x * blockDim.x + threadIdx.x;
    if (i >= BB * SS * EE) return;
    int tok = i / EE;
    int e = i % EE;
    out[i] = table[(size_t)ids[tok] * EE + e];
}

__global__ void embed_dec_kernel(const int* __restrict__ tgt,
                                 const float* __restrict__ table,
                                 float* __restrict__ out) {
    int i = blockIdx.x * blockDim.x + threadIdx.x;
    if (i >= TM * BB * EE) return;
    int m = i / EE;
    int e = i % EE;
    int t = m / BB;
    int b = m % BB;
    out[i] = table[(size_t)tgt[b * TT + t] * EE + e];
}

// one launch transposes all 6 recurrent weight matrices (all [3H x H]): Wt[k][n]=W[n][k]
__global__ void transpose_all(const float* __restrict__ w0, const float* __restrict__ w1,
                              const float* __restrict__ w2, const float* __restrict__ w3,
                              const float* __restrict__ w4, const float* __restrict__ w5,
                              float* __restrict__ wt_base) {
    __shared__ float s[32][33];
    const int z = blockIdx.z;
    const float* W = (z == 0) ? w0 : (z == 1) ? w1 : (z == 2) ? w2
                   : (z == 3) ? w3 : (z == 4) ? w4 : w5;
    float* Wt = wt_base + (size_t)z * WT_SZ;
    int n0 = blockIdx.x * 32, k0 = blockIdx.y * 32;
    int tx = threadIdx.x & 31, ty = threadIdx.x >> 5;
#pragma unroll
    for (int i = 0; i < 4; i++)
        s[ty + i * 8][tx] = W[(size_t)(n0 + ty + i * 8) * HH + k0 + tx];
    __syncthreads();
#pragma unroll
    for (int i = 0; i < 4; i++)
        Wt[(size_t)(k0 + ty + i * 8) * H3 + n0 + tx] = s[tx][ty + i * 8];
}

// ---------------- tf32 helpers ----------------
__device__ __forceinline__ uint32_t f2tf(float f) {
    uint32_t u;
    asm("cvt.rna.tf32.f32 %0, %1;" : "=r"(u) : "f"(f));
    return u;
}

// ---------------- tf32 GEMM (batched projections; 128x128, 4 warps) ----------------
#define MODE_NORM 0
#define MODE_TENC 2   // m = b*64+t -> out row t*32+b (row-major [t][b][n])

template <int MODE>
__global__ void __launch_bounds__(256)
gemm_tf32(const float* __restrict__ A, int lda,
          const float* __restrict__ W, int ldw,
          const float* __restrict__ bias,
          float* __restrict__ C, int M, int N, int K) {
    __shared__ uint32_t As[32][132];   // [k][m]
    __shared__ uint32_t Ws[32][132];   // [k][n]
    const int bm = blockIdx.y * 128, bn = blockIdx.x * 128;
    const int tid = threadIdx.x;
    const int warp = tid >> 5, lane = tid & 31;
    const int wm = (warp & 1) * 64, wn = (warp >> 1) * 32;
    const int g = lane >> 2, tig = lane & 3;

    float acc[4][4][4];
#pragma unroll
    for (int a = 0; a < 4; a++)
#pragma unroll
        for (int b = 0; b < 4; b++)
#pragma unroll
            for (int c = 0; c < 4; c++) acc[a][b][c] = 0.f;

    float4 pa[4], pw[4];
#pragma unroll
    for (int i = 0; i < 4; i++) {
        int e = tid + i * 256;
        int m = e >> 3, kq = (e & 7) * 4;
        float4 v = make_float4(0.f, 0.f, 0.f, 0.f);
        if (bm + m < M) v = ld4(A + (size_t)(bm + m) * lda + kq);
        pa[i] = v;
        pw[i] = ld4(W + (size_t)(bn + m) * ldw + kq);
    }
#pragma unroll
    for (int i = 0; i < 4; i++) {
        int e = tid + i * 256;
        int m = e >> 3, kq = (e & 7) * 4;
        As[kq + 0][m] = f2tf(pa[i].x); As[kq + 1][m] = f2tf(pa[i].y);
        As[kq + 2][m] = f2tf(pa[i].z); As[kq + 3][m] = f2tf(pa[i].w);
        Ws[kq + 0][m] = f2tf(pw[i].x); Ws[kq + 1][m] = f2tf(pw[i].y);
        Ws[kq + 2][m] = f2tf(pw[i].z); Ws[kq + 3][m] = f2tf(pw[i].w);
    }
    __syncthreads();

    for (int k0 = 0; k0 < K; k0 += 32) {
        bool has_next = (k0 + 32) < K;
        if (has_next) {
#pragma unroll
            for (int i = 0; i < 4; i++) {
                int e = tid + i * 256;
                int m = e >> 3, kq = (e & 7) * 4;
                float4 v = make_float4(0.f, 0.f, 0.f, 0.f);
                if (bm + m < M) v = ld4(A + (size_t)(bm + m) * lda + k0 + 32 + kq);
                pa[i] = v;
                pw[i] = ld4(W + (size_t)(bn + m) * ldw + k0 + 32 + kq);
            }
        }
#pragma unroll
        for (int kk = 0; kk < 32; kk += 8) {
            uint32_t af[4][4];
#pragma unroll
            for (int mt = 0; mt < 4; mt++) {
                int ml = wm + mt * 16 + g;
                af[mt][0] = As[kk + tig][ml];
                af[mt][1] = As[kk + tig][ml + 8];
                af[mt][2] = As[kk + tig + 4][ml];
                af[mt][3] = As[kk + tig + 4][ml + 8];
            }
            uint32_t bf[4][2];
#pragma unroll
            for (int nt = 0; nt < 4; nt++) {
                int nl = wn + nt * 8 + g;
                bf[nt][0] = Ws[kk + tig][nl];
                bf[nt][1] = Ws[kk + tig + 4][nl];
            }
#pragma unroll
            for (int mt = 0; mt < 4; mt++)
#pragma unroll
                for (int nt = 0; nt < 4; nt++) {
                    asm volatile(
                        "mma.sync.aligned.m16n8k8.row.col.f32.tf32.tf32.f32 "
                        "{%0,%1,%2,%3}, {%4,%5,%6,%7}, {%8,%9}, {%0,%1,%2,%3};\n"
                        : "+f"(acc[mt][nt][0]), "+f"(acc[mt][nt][1]),
                          "+f"(acc[mt][nt][2]), "+f"(acc[mt][nt][3])
                        : "r"(af[mt][0]), "r"(af[mt][1]), "r"(af[mt][2]), "r"(af[mt][3]),
                          "r"(bf[nt][0]), "r"(bf[nt][1]));
                }
        }
        __syncthreads();
        if (has_next) {
#pragma unroll
            for (int i = 0; i < 4; i++) {
                int e = tid + i * 256;
                int m = e >> 3, kq = (e & 7) * 4;
                As[kq + 0][m] = f2tf(pa[i].x); As[kq + 1][m] = f2tf(pa[i].y);
                As[kq + 2][m] = f2tf(pa[i].z); As[kq + 3][m] = f2tf(pa[i].w);
                Ws[kq + 0][m] = f2tf(pw[i].x); Ws[kq + 1][m] = f2tf(pw[i].y);
                Ws[kq + 2][m] = f2tf(pw[i].z); Ws[kq + 3][m] = f2tf(pw[i].w);
            }
            __syncthreads();
        }
    }

#pragma unroll
    for (int mt = 0; mt < 4; mt++) {
#pragma unroll
        for (int i2 = 0; i2 < 2; i2++) {
            int m = bm + wm + mt * 16 + g + i2 * 8;
            if (m >= M) continue;
            size_t row;
            if (MODE == MODE_TENC) {
                int t = m & 63, b = m >> 6;
                row = (size_t)(t * BB + b);
            } else {
                row = (size_t)m;
            }
            float* cr = C + row * N;
#pragma unroll
            for (int nt = 0; nt < 4; nt++) {
#pragma unroll
                for (int j = 0; j < 2; j++) {
                    int n = bn + wn + nt * 8 + tig * 2 + j;
                    float v = acc[mt][nt][i2 * 2 + j];
                    if (bias) v += bias[n];
                    cr[n] = v;
                }
            }
        }
    }
}

// ---------------- final projection: cp.async double-buffered, 128x256, 8 warps ----------------
#define FSM_STAGE_WORDS (128 * 36 + 256 * 36)     // 13824 words = 55296 B per stage
#define FSM2_BYTES (2 * FSM_STAGE_WORDS * 4)      // 110592 B

__device__ __forceinline__ void cp16(uint32_t daddr, const void* src, bool pred) {
    int sz = pred ? 16 : 0;
    asm volatile("cp.async.cg.shared.global [%0], [%1], 16, %2;\n"
                 :: "r"(daddr), "l"(src), "r"(sz));
}

__global__ void __launch_bounds__(256)
gemm_final(const float* __restrict__ A, int lda,
           const float* __restrict__ W, int ldw,
           const float* __restrict__ bias,
           float* __restrict__ C, int M, int N, int K) {
    extern __shared__ uint32_t sm[];
    uint32_t sbase;
    asm("{ .reg .u64 t; cvta.to.shared.u64 t, %1; cvt.u32.u64 %0, t; }"
        : "=r"(sbase) : "l"(sm));

    const int bm = blockIdx.x * 128;   // m-major: W streams from DRAM once
    const int bn = blockIdx.y * 256;
    const int tid = threadIdx.x;
    const int warp = tid >> 5, lane = tid & 31;
    const int wm = (warp & 1) * 64, wn = (warp >> 1) * 64;
    const int g = lane >> 2, tig = lane & 3;
    const int kq = (tid & 7) * 4;

    float acc[4][8][4];
#pragma unroll
    for (int a = 0; a < 4; a++)
#pragma unroll
        for (int b = 0; b < 8; b++)
#pragma unroll
            for (int c = 0; c < 4; c++) acc[a][b][c] = 0.f;

    // issue all 12 cp.asyncs for one stage/chunk, then commit
#define ISSUE_STAGE(S, K0)                                                     \
    do {                                                                       \
        uint32_t asb = sbase + (uint32_t)(S) * (FSM_STAGE_WORDS * 4);          \
        uint32_t wsb = asb + 128 * 36 * 4;                                     \
        _Pragma("unroll") for (int i = 0; i < 4; i++) {                        \
            int e = tid + i * 256;                                             \
            int m = e >> 3;                                                    \
            cp16(asb + (uint32_t)(m * 36 + kq) * 4,                            \
                 A + (size_t)(bm + m) * lda + (K0) + kq, (bm + m) < M);        \
        }                                                                      \
        _Pragma("unroll") for (int i = 0; i < 8; i++) {                        \
            int e = tid + i * 256;                                             \
            int n = e >> 3;                                                    \
            cp16(wsb + (uint32_t)(n * 36 + kq) * 4,                            \
                 W + (size_t)(bn + n) * ldw + (K0) + kq, true);                \
        }                                                                      \
        asm volatile("cp.async.commit_group;\n");                              \
    } while (0)

    ISSUE_STAGE(0, 0);
    int cur = 0;

    for (int k0 = 0; k0 < K; k0 += 32) {
        bool has_next = (k0 + 32) < K;
        if (has_next) ISSUE_STAGE(cur ^ 1, k0 + 32);
        if (has_next)
            asm volatile("cp.async.wait_group 1;\n");
        else
            asm volatile("cp.async.wait_group 0;\n");
        __syncthreads();

        const uint32_t* As = sm + (size_t)cur * FSM_STAGE_WORDS;       // [128][36]
        const uint32_t* Ws = As + 128 * 36;                            // [256][36]
#pragma unroll
        for (int kk = 0; kk < 32; kk += 8) {
            uint32_t af[4][4];
#pragma unroll
            for (int mt = 0; mt < 4; mt++) {
                int ml = wm + mt * 16 + g;
                af[mt][0] = As[ml * 36 + kk + tig];
                af[mt][1] = As[(ml + 8) * 36 + kk + tig];
                af[mt][2] = As[ml * 36 + kk + tig + 4];
                af[mt][3] = As[(ml + 8) * 36 + kk + tig + 4];
            }
            uint32_t bf[8][2];
#pragma unroll
            for (int nt = 0; nt < 8; nt++) {
                int nl = wn + nt * 8 + g;
                bf[nt][0] = Ws[nl * 36 + kk + tig];
                bf[nt][1] = Ws[nl * 36 + kk + tig + 4];
            }
#pragma unroll
            for (int mt = 0; mt < 4; mt++)
#pragma unroll
                for (int nt = 0; nt < 8; nt++) {
                    asm volatile(
                        "mma.sync.aligned.m16n8k8.row.col.f32.tf32.tf32.f32 "
                        "{%0,%1,%2,%3}, {%4,%5,%6,%7}, {%8,%9}, {%0,%1,%2,%3};\n"
                        : "+f"(acc[mt][nt][0]), "+f"(acc[mt][nt][1]),
                          "+f"(acc[mt][nt][2]), "+f"(acc[mt][nt][3])
                        : "r"(af[mt][0]), "r"(af[mt][1]), "r"(af[mt][2]), "r"(af[mt][3]),
                          "r"(bf[nt][0]), "r"(bf[nt][1]));
                }
        }
        __syncthreads();
        cur ^= 1;
    }

    // epilogue: rows m = t*32+b -> out row b*TM + t
#pragma unroll
    for (int mt = 0; mt < 4; mt++) {
#pragma unroll
        for (int i2 = 0; i2 < 2; i2++) {
            int m = bm + wm + mt * 16 + g + i2 * 8;
            if (m >= M) continue;
            int b = m & 31, t = m >> 5;
            float* cr = C + (size_t)(b * TM + t) * N;
#pragma unroll
            for (int nt = 0; nt < 8; nt++) {
#pragma unroll
                for (int j = 0; j < 2; j++) {
                    int n = bn + wn + nt * 8 + tig * 2 + j;
                    cr[n] = acc[mt][nt][i2 * 2 + j] + bias[n];
                }
            }
        }
    }
#undef ISSUE_STAGE
}

// ---------------- tf32 recurrent GEMM body: M=32, n-tile 128, k-chunk 256 ----------------
// At row-major [32][HH] fp32; Wt [k][n] stride H3. Writes slab [b][n] row-major.
__device__ __forceinline__ void rec_mma_body(
    const float* __restrict__ At, const float* __restrict__ Wt,
    float* __restrict__ P,
    uint32_t (*As)[33], uint32_t (*Ws)[132],
    int tid, int n0, int k0) {
    const int warp = tid >> 5, lane = tid & 31;
    const int wn = warp * 16;           // 8 warps x n16
    const int g = lane >> 2, tig = lane & 3;
    const int am = tid >> 3, akq = (tid & 7) * 4;

    float acc[2][2][4];
#pragma unroll
    for (int a = 0; a < 2; a++)
#pragma unroll
        for (int b = 0; b < 2; b++)
#pragma unroll
            for (int c = 0; c < 4; c++) acc[a][b][c] = 0.f;

    float4 pa;
    float4 pw[4];
    pa = ld4(At + (size_t)am * HH + k0 + akq);
#pragma unroll
    for (int i = 0; i < 4; i++) {
        int e = tid + i * 256;
        pw[i] = ld4(Wt + (size_t)(k0 + (e >> 5)) * H3 + n0 + (e & 31) * 4);
    }
    As[akq + 0][am] = f2tf(pa.x); As[akq + 1][am] = f2tf(pa.y);
    As[akq + 2][am] = f2tf(pa.z); As[akq + 3][am] = f2tf(pa.w);
#pragma unroll
    for (int i = 0; i < 4; i++) {
        int e = tid + i * 256;
        uint4 u = make_uint4(f2tf(pw[i].x), f2tf(pw[i].y), f2tf(pw[i].z), f2tf(pw[i].w));
        *reinterpret_cast<uint4*>(&Ws[e >> 5][(e & 31) * 4]) = u;
    }
    __syncthreads();

    for (int c = 0; c < 8; c++) {
        bool has_next = c < 7;
        if (has_next) {
            int kn = k0 + (c + 1) * 32;
            pa = ld4(At + (size_t)am * HH + kn + akq);
#pragma unroll
            for (int i = 0; i < 4; i++) {
                int e = tid + i * 256;
                pw[i] = ld4(Wt + (size_t)(kn + (e >> 5)) * H3 + n0 + (e & 31) * 4);
            }
        }
#pragma unroll
        for (int kk = 0; kk < 32; kk += 8) {
            uint32_t af[2][4];
#pragma unroll
            for (int mt = 0; mt < 2; mt++) {
                int ml = mt * 16 + g;
                af[mt][0] = As[kk + tig][ml];
                af[mt][1] = As[kk + tig][ml + 8];
                af[mt][2] = As[kk + tig + 4][ml];
                af[mt][3] = As[kk + tig + 4][ml + 8];
            }
            uint32_t bf[2][2];
#pragma unroll
            for (int nt = 0; nt < 2; nt++) {
                int nl = wn + nt * 8 + g;
                bf[nt][0] = Ws[kk + tig][nl];
                bf[nt][1] = Ws[kk + tig + 4][nl];
            }
#pragma unroll
            for (int mt = 0; mt < 2; mt++)
#pragma unroll
                for (int nt = 0; nt < 2; nt++) {
                    asm volatile(
                        "mma.sync.aligned.m16n8k8.row.col.f32.tf32.tf32.f32 "
                        "{%0,%1,%2,%3}, {%4,%5,%6,%7}, {%8,%9}, {%0,%1,%2,%3};\n"
                        : "+f"(acc[mt][nt][0]), "+f"(acc[mt][nt][1]),
                          "+f"(acc[mt][nt][2]), "+f"(acc[mt][nt][3])
                        : "r"(af[mt][0]), "r"(af[mt][1]), "r"(af[mt][2]), "r"(af[mt][3]),
                          "r"(bf[nt][0]), "r"(bf[nt][1]));
                }
        }
        __syncthreads();
        if (has_next) {
            As[akq + 0][am] = f2tf(pa.x); As[akq + 1][am] = f2tf(pa.y);
            As[akq + 2][am] = f2tf(pa.z); As[akq + 3][am] = f2tf(pa.w);
#pragma unroll
            for (int i = 0; i < 4; i++) {
                int e = tid + i * 256;
                uint4 u = make_uint4(f2tf(pw[i].x), f2tf(pw[i].y),
                                     f2tf(pw[i].z), f2tf(pw[i].w));
                *reinterpret_cast<uint4*>(&Ws[e >> 5][(e & 31) * 4]) = u;
            }
            __syncthreads();
        }
    }

    // epilogue: acc rows -> slab [b][n]
#pragma unroll
    for (int mt = 0; mt < 2; mt++) {
#pragma unroll
        for (int i2 = 0; i2 < 2; i2++) {
            int b = mt * 16 + g + i2 * 8;
            float* pr = P + (size_t)b * H3 + n0 + wn;
#pragma unroll
            for (int nt = 0; nt < 2; nt++) {
#pragma unroll
                for (int j = 0; j < 2; j++)
                    pr[nt * 8 + tig * 2 + j] = acc[mt][nt][i2 * 2 + j];
            }
        }
    }
}

// encoder wavefront rec: z0 h0@ewhh0 (slabs0-3), z1 h0@ewih1 (4-7), z2 h1@ewhh1 (8-11)
__global__ void __launch_bounds__(256)
enc_rec(const float* __restrict__ h0c, const float* __restrict__ h1c,
        const float* __restrict__ wt_whh0, const float* __restrict__ wt_wih1,
        const float* __restrict__ wt_whh1, float* __restrict__ part) {
    __shared__ uint32_t As[32][33];
    __shared__ uint32_t Ws[32][132];
    const int z = blockIdx.z;
    const float* A = (z == 2) ? h1c : h0c;
    const float* W = (z == 0) ? wt_whh0 : (z == 1) ? wt_wih1 : wt_whh1;
    rec_mma_body(A, W, part + (size_t)(z * KSPLIT + blockIdx.y) * PARTSZ,
                 As, Ws, threadIdx.x, blockIdx.x * 128, blockIdx.y * 256);
}

// encoder wavefront gate: blocks 0-127 layer0 (t0), 128-255 layer1 (t1)
__global__ void __launch_bounds__(256)
enc_gate(const float* __restrict__ part,
         const float* __restrict__ gi0,      // [t][b][n]
         const float* __restrict__ bhh0, const float* __restrict__ bih1,
         const float* __restrict__ bhh1,
         const float* __restrict__ h0c, float* __restrict__ h0n,
         const float* __restrict__ h1c, float* __restrict__ h1n,
         float* __restrict__ encout,
         int t0, int t0v, int t1, int t1v) {
    const int lay = blockIdx.x >> 7;
    const int lb = blockIdx.x & 127;
    const int b = lb >> 2;
    const int h = (lb & 3) * 256 + threadIdx.x;
    if (lay == 0) {
        if (!t0v) return;
        const float* G = gi0 + ((size_t)t0 * BB + b) * H3;
        float gr = G[h], gz = G[HH + h], gn = G[2 * HH + h];
        float hr = bhh0[h], hz = bhh0[HH + h], hn = bhh0[2 * HH + h];
#pragma unroll
        for (int j = 0; j < KSPLIT; j++) {
            const float* P = part + (size_t)j * PARTSZ + (size_t)b * H3;
            hr += P[h]; hz += P[HH + h]; hn += P[2 * HH + h];
        }
        float r = 1.f / (1.f + expf(-(gr + hr)));
        float z = 1.f / (1.f + expf(-(gz + hz)));
        float n = tanhf(gn + r * hn);
        float hp = h0c[(size_t)b * HH + h];
        h0n[(size_t)b * HH + h] = (1.f - z) * n + z * hp;
    } else {
        if (!t1v) return;
        float gr = bih1[h], gz = bih1[HH + h], gn = bih1[2 * HH + h];
        float hr = bhh1[h], hz = bhh1[HH + h], hn = bhh1[2 * HH + h];
#pragma unroll
        for (int j = 0; j < KSPLIT; j++) {
            const float* Px = part + (size_t)(KSPLIT + j) * PARTSZ + (size_t)b * H3;
            const float* Ph = part + (size_t)(2 * KSPLIT + j) * PARTSZ + (size_t)b * H3;
            gr += Px[h]; gz += Px[HH + h]; gn += Px[2 * HH + h];
            hr += Ph[h]; hz += Ph[HH + h]; hn += Ph[2 * HH + h];
        }
        float r = 1.f / (1.f + expf(-(gr + hr)));
        float z = 1.f / (1.f + expf(-(gz + hz)));
        float n = tanhf(gn + r * hn);
        float hp = h1c[(size_t)b * HH + h];
        float out = (1.f - z) * n + z * hp;
        h1n[(size_t)b * HH + h] = out;
        encout[((size_t)b * SS + t1) * HH + h] = out;
    }
}

// decoder launch A: blocks 0-31 attention; 32+: rec z0 h0@dwhh0 (slabs0-3), z1 h1@dwhh1 (4-7)
__global__ void __launch_bounds__(256)
dec_A(const float* __restrict__ proj, const float* __restrict__ d1,
      const int* __restrict__ src_ids, float* __restrict__ attw,
      const float* __restrict__ h0c, const float* __restrict__ h1c,
      const float* __restrict__ wt_whh0, const float* __restrict__ wt_whh1,
      float* __restrict__ part) {
    __shared__ uint32_t As[32][33];
    __shared__ uint32_t Ws[32][132];
    const int bid = blockIdx.x;
    const int tid = threadIdx.x;
    if (bid < 32) {
        float* sc = reinterpret_cast<float*>(Ws);
        const int b = bid;
        const int lane = tid & 31, warp = tid >> 5;
        const float* d1b = d1 + (size_t)b * HH;
        for (int s = warp; s < SS; s += 8) {
            const float* pr = proj + ((size_t)b * SS + s) * HH;
            float p = 0.f;
#pragma unroll
            for (int j = 0; j < 8; j++) {
                int k0 = j * 128 + lane * 4;
                float4 dv = ld4(d1b + k0);
                float4 pv = ld4(pr + k0);
                p += dv.x * pv.x + dv.y * pv.y + dv.z * pv.z + dv.w * pv.w;
            }
#pragma unroll
            for (int o = 16; o; o >>= 1) p += __shfl_xor_sync(0xffffffffu, p, o);
            if (lane == 0) sc[s] = (src_ids[b * SS + s] != 0) ? p : -1e9f;
        }
        __syncthreads();
        if (warp == 0) {
            float v0 = sc[lane], v1 = sc[lane + 32];
            float m = fmaxf(v0, v1);
#pragma unroll
            for (int o = 16; o; o >>= 1) m = fmaxf(m, __shfl_xor_sync(0xffffffffu, m, o));
            float e0 = expf(v0 - m), e1 = expf(v1 - m);
            float su = e0 + e1;
#pragma unroll
            for (int o = 16; o; o >>= 1) su += __shfl_xor_sync(0xffffffffu, su, o);
            attw[b * SS + lane] = e0 / su;
            attw[b * SS + lane + 32] = e1 / su;
        }
    } else {
        const int e = bid - 32;          // 0..191
        const int z = e / 96;            // 0: h0@whh0, 1: h1@whh1
        const int r = e % 96;
        const int n0 = (r % 24) * 128;
        const int kc = r / 24;           // 0..3
        const float* A = z ? h1c : h0c;
        const float* W = z ? wt_whh1 : wt_whh0;
        rec_mma_body(A, W, part + (size_t)(z * KSPLIT + kc) * PARTSZ,
                     As, Ws, tid, n0, kc * 256);
    }
}

// decoder gate0: gi = epre + Σ_s attw*encV ; h-side = slabs 0-3
__global__ void __launch_bounds__(256)
dec_gate0(const float* __restrict__ part,
          const float* __restrict__ epre_t,   // [b][n]
          const float* __restrict__ encV,     // [b][s][n]
          const float* __restrict__ attw,
          const float* __restrict__ bhh0,
          const float* __restrict__ h0c, float* __restrict__ h0n) {
    __shared__ float aw[SS];
    const int b = blockIdx.x >> 2;
    const int h = (blockIdx.x & 3) * 256 + threadIdx.x;
    if (threadIdx.x < SS) aw[threadIdx.x] = attw[b * SS + threadIdx.x];
    __syncthreads();
    const float* G = epre_t + (size_t)b * H3;
    float gr = G[h], gz = G[HH + h], gn = G[2 * HH + h];
    const float* V = encV + (size_t)b * SS * H3;
#pragma unroll 4
    for (int s = 0; s < SS; s++) {
        float w = aw[s];
        const float* vr = V + (size_t)s * H3;
        gr += w * vr[h];
        gz += w * vr[HH + h];
        gn += w * vr[2 * HH + h];
    }
    float hr = bhh0[h], hz = bhh0[HH + h], hn = bhh0[2 * HH + h];
#pragma unroll
    for (int j = 0; j < KSPLIT; j++) {
        const float* P = part + (size_t)j * PARTSZ + (size_t)b * H3;
        hr += P[h]; hz += P[HH + h]; hn += P[2 * HH + h];
    }
    float r = 1.f / (1.f + expf(-(gr + hr)));
    float z = 1.f / (1.f + expf(-(gz + hz)));
    float n = tanhf(gn + r * hn);
    float hp = h0c[(size_t)b * HH + h];
    h0n[(size_t)b * HH + h] = (1.f - z) * n + z * hp;
}

// decoder launch C: rec h0'@dwih1 -> slabs 8-11
__global__ void __launch_bounds__(256)
dec_C(const float* __restrict__ h0n, const float* __restrict__ wt_wih1,
      float* __restrict__ part) {
    __shared__ uint32_t As[32][33];
    __shared__ uint32_t Ws[32][132];
    rec_mma_body(h0n, wt_wih1, part + (size_t)(2 * KSPLIT + blockIdx.y) * PARTSZ,
                 As, Ws, threadIdx.x, blockIdx.x * 128, blockIdx.y * 256);
}

// decoder gate1: x = slabs 8-11 + bih1; h = slabs 4-7 + bhh1; writes h1', cat [d1|ctx]
__global__ void __launch_bounds__(256)
dec_gate1(const float* __restrict__ part,
          const float* __restrict__ bih1, const float* __restrict__ bhh1,
          const float* __restrict__ encout,   // [b][s][h]
          const float* __restrict__ attw,
          const float* __restrict__ h1c, float* __restrict__ h1n,
          float* __restrict__ cat_t) {
    __shared__ float aw[SS];
    const int b = blockIdx.x >> 2;
    const int h = (blockIdx.x & 3) * 256 + threadIdx.x;
    if (threadIdx.x < SS) aw[threadIdx.x] = attw[b * SS + threadIdx.x];
    __syncthreads();
    float gr = bih1[h], gz = bih1[HH + h], gn = bih1[2 * HH + h];
    float hr = bhh1[h], hz = bhh1[HH + h], hn = bhh1[2 * HH + h];
#pragma unroll
    for (int j = 0; j < KSPLIT; j++) {
        const float* Px = part + (size_t)(2 * KSPLIT + j) * PARTSZ + (size_t)b * H3;
        const float* Ph = part + (size_t)(KSPLIT + j) * PARTSZ + (size_t)b * H3;
        gr += Px[h]; gz += Px[HH + h]; gn += Px[2 * HH + h];
        hr += Ph[h]; hz += Ph[HH + h]; hn += Ph[2 * HH + h];
    }
    float r = 1.f / (1.f + expf(-(gr + hr)));
    float z = 1.f / (1.f + expf(-(gz + hz)));
    float n = tanhf(gn + r * hn);
    float hp = h1c[(size_t)b * HH + h];
    float out = (1.f - z) * n + z * hp;
    h1n[(size_t)b * HH + h] = out;
    cat_t[(size_t)b * H2 + h] = out;
    const float* E = encout + (size_t)b * SS * HH;
    float c = 0.f;
#pragma unroll 8
    for (int s = 0; s < SS; s++) c += aw[s] * E[(size_t)s * HH + h];
    cat_t[(size_t)b * H2 + HH + h] = c;
}

// ---------------- host launcher ----------------
extern "C" void kernel_launch(void* const* d_in, const int* in_sizes, int n_in,
                              void* d_out, int out_size) {
    const int*   src_ids  = (const int*)d_in[0];
    const int*   tgt_ids  = (const int*)d_in[2];
    const float* enc_emb  = (const float*)d_in[3];
    const float* dec_emb  = (const float*)d_in[4];
    const float* enc_wih0 = (const float*)d_in[5];
    const float* enc_whh0 = (const float*)d_in[6];
    const float* enc_bih0 = (const float*)d_in[7];
    const float* enc_bhh0 = (const float*)d_in[8];
    const float* enc_wih1 = (const float*)d_in[9];
    const float* enc_whh1 = (const float*)d_in[10];
    const float* enc_bih1 = (const float*)d_in[11];
    const float* enc_bhh1 = (const float*)d_in[12];
    const float* dec_wih0 = (const float*)d_in[13];
    const float* dec_whh0 = (const float*)d_in[14];
    const float* dec_bih0 = (const float*)d_in[15];
    const float* dec_bhh0 = (const float*)d_in[16];
    const float* dec_wih1 = (const float*)d_in[17];
    const float* dec_whh1 = (const float*)d_in[18];
    const float* dec_bih1 = (const float*)d_in[19];
    const float* dec_bhh1 = (const float*)d_in[20];
    const float* attn_w   = (const float*)d_in[21];
    const float* out_w    = (const float*)d_in[22];
    const float* out_b    = (const float*)d_in[23];
    float* out = (float*)d_out;

    float* base = nullptr;
    cudaGetSymbolAddress((void**)&base, g_scratch);
    float* embS   = base + OFF_EMBS;
    float* gi0    = base + OFF_GI0;
    float* encout = base + OFF_ENCOUT;
    float* proj   = base + OFF_PROJ;
    float* encV   = base + OFF_ENCV;
    float* embT   = base + OFF_EMBT;
    float* epre   = base + OFF_EPRE;
    float* cat    = base + OFF_CAT;
    float* h0A    = base + OFF_H0A;
    float* h0B    = base + OFF_H0B;
    float* h1A    = base + OFF_H1A;
    float* h1B    = base + OFF_H1B;
    float* attw   = base + OFF_ATTW;
    float* part   = base + OFF_PART;
    float* wt_ewhh0 = base + OFF_WT + 0 * WT_SZ;
    float* wt_ewhh1 = base + OFF_WT + 1 * WT_SZ;
    float* wt_ewih1 = base + OFF_WT + 2 * WT_SZ;
    float* wt_dwhh0 = base + OFF_WT + 3 * WT_SZ;
    float* wt_dwhh1 = base + OFF_WT + 4 * WT_SZ;
    float* wt_dwih1 = base + OFF_WT + 5 * WT_SZ;

    cudaFuncSetAttribute(gemm_final, cudaFuncAttributeMaxDynamicSharedMemorySize, FSM2_BYTES);

    transpose_all<<<dim3(H3 / 32, HH / 32, 6), 256>>>(
        enc_whh0, enc_whh1, enc_wih1, dec_whh0, dec_whh1, dec_wih1, base + OFF_WT);
    embed_enc_kernel<<<(BB * SS * EE + 255) / 256, 256>>>(src_ids, enc_emb, embS);
    embed_dec_kernel<<<(TM * BB * EE + 255) / 256, 256>>>(tgt_ids, dec_emb, embT);
    gemm_tf32<MODE_TENC><<<dim3(H3 / 128, 16), 256>>>(
        embS, EE, enc_wih0, EE, enc_bih0, gi0, BB * SS, H3, EE);
    zero_kernel<<<(4 * BB * HH + 255) / 256, 256>>>(h0A, 4 * BB * HH);
    // epre = embT @ dec_wih0[:, :E]^T + dec_bih0 -> [t][b][n]
    gemm_tf32<MODE_NORM><<<dim3(H3 / 128, (TM * BB + 127) / 128), 256>>>(
        embT, EE, dec_wih0, EE + HH, dec_bih0, epre, TM * BB, H3, EE);

    float* h0_cur = h0A; float* h0_nxt = h0B;
    float* h1_cur = h1A; float* h1_nxt = h1B;

    // ---- encoder wavefront: 65 stages, 2 launches each ----
    for (int s = 0; s <= SS; s++) {
        enc_rec<<<dim3(24, KSPLIT, 3), 256>>>(h0_cur, h1_cur,
                                              wt_ewhh0, wt_ewih1, wt_ewhh1, part);
        enc_gate<<<256, 256>>>(part, gi0, enc_bhh0, enc_bih1, enc_bhh1,
                               h0_cur, h0_nxt, h1_cur, h1_nxt, encout,
                               s, (s < SS) ? 1 : 0, s - 1, (s > 0) ? 1 : 0);
        if (s < SS) { float* tmp = h0_cur; h0_cur = h0_nxt; h0_nxt = tmp; }
        if (s > 0)  { float* tmp = h1_cur; h1_cur = h1_nxt; h1_nxt = tmp; }
    }

    // proj = encout @ attn_w^T ; encV = encout @ dec_wih0[:, E:]^T
    gemm_tf32<MODE_NORM><<<dim3(HH / 128, 16), 256>>>(
        encout, HH, attn_w, HH, nullptr, proj, BB * SS, HH, HH);
    gemm_tf32<MODE_NORM><<<dim3(H3 / 128, 16), 256>>>(
        encout, HH, dec_wih0 + EE, EE + HH, nullptr, encV, BB * SS, H3, HH);

    // ---- decoder loop: 4 launches per step ----
    for (int t = 0; t < TM; t++) {
        float* epre_t = epre + (size_t)t * BB * H3;
        float* cat_t  = cat + (size_t)t * BB * H2;
        dec_A<<<32 + 2 * 96, 256>>>(proj, h1_cur, src_ids, attw,
                                    h0_cur, h1_cur, wt_dwhh0, wt_dwhh1, part);
        dec_gate0<<<128, 256>>>(part, epre_t, encV, attw, dec_bhh0, h0_cur, h0_nxt);
        dec_C<<<dim3(24, KSPLIT), 256>>>(h0_nxt, wt_dwih1, part);
        dec_gate1<<<128, 256>>>(part, dec_bih1, dec_bhh1, encout, attw,
                                h1_cur, h1_nxt, cat_t);
        float* tmp;
        tmp = h0_cur; h0_cur = h0_nxt; h0_nxt = tmp;
        tmp = h1_cur; h1_cur = h1_nxt; h1_nxt = tmp;
    }

    // ---- final projection: logits = cat @ out_w^T + out_b -> (B, TM, V) ----
    gemm_final<<<dim3((TM * BB + 127) / 128, VV / 256), 256, FSM2_BYTES>>>(
        cat, H2, out_w, H2, out_b, out, TM * BB, VV, H2);
}

// round 12
// speedup vs baseline: 1.0008x; 1.0008x over previous
#include <cuda_runtime.h>
#include <cstdint>

// Problem dims
#define BB 32
#define SS 64
#define TT 48
#define TM 47      // T-1 decoder steps
#define VV 32000
#define EE 512
#define HH 1024
#define H3 3072
#define H2 2048
#define KSPLIT 4
#define PARTSZ ((size_t)BB * H3)

// ---------------- scratch (device global, no allocs) ----------------
#define OFF_EMBS   0ull                                   // [b][s][e]
#define OFF_GI0    (OFF_EMBS   + (size_t)BB*SS*EE)        // [t][b][n]
#define OFF_ENCOUT (OFF_GI0    + (size_t)BB*SS*H3)        // [b][t][h]
#define OFF_PROJ   (OFF_ENCOUT + (size_t)BB*SS*HH)        // [b][s][h]
#define OFF_ENCV   (OFF_PROJ   + (size_t)BB*SS*HH)        // [b][s][n]  encout @ Wc^T
#define OFF_EMBT   (OFF_ENCV   + (size_t)BB*SS*H3)        // rows m=t*B+b
#define OFF_EPRE   (OFF_EMBT   + (size_t)TM*BB*EE)        // [t][b][n]
#define OFF_CAT    (OFF_EPRE   + (size_t)TM*BB*H3)        // rows m=t*B+b, [d1|ctx]
#define OFF_H0A    (OFF_CAT    + (size_t)TM*BB*H2)        // state [b][h] row-major
#define OFF_H0B    (OFF_H0A    + (size_t)BB*HH)
#define OFF_H1A    (OFF_H0B    + (size_t)BB*HH)
#define OFF_H1B    (OFF_H1A    + (size_t)BB*HH)
#define OFF_ATTW   (OFF_H1B    + (size_t)BB*HH)           // attn weights [b][64]
#define OFF_PART   (OFF_ATTW   + (size_t)BB*SS)           // 12 partial slabs [b][n]
#define OFF_WT     (OFF_PART   + 12*PARTSZ)               // 6 transposed weights [k][n]
#define WT_SZ      ((size_t)HH * H3)
#define SCRATCH_TOTAL (OFF_WT + 6*WT_SZ)

__device__ float g_scratch[SCRATCH_TOTAL];

// ---------------- small helpers ----------------
__device__ __forceinline__ float4 ld4(const float* p) {
    return *reinterpret_cast<const float4*>(p);
}
__device__ __forceinline__ void st4(float* p, float4 v) {
    *reinterpret_cast<float4*>(p) = v;
}

__global__ void zero_kernel(float* p, int n) {
    int i = blockIdx.x * blockDim.x + threadIdx.x;
    if (i < n) p[i] = 0.f;
}

__global__ void embed_enc_kernel(const int* __restrict__ ids,
                                 const float* __restrict__ table,
                                 float* __restrict__ out) {
    int i = blockIdx.x * blockDim.x + threadIdx.x;
    if (i >= BB * SS * EE) return;
    int tok = i / EE;
    int e = i % EE;
    out[i] = table[(size_t)ids[tok] * EE + e];
}

__global__ void embed_dec_kernel(const int* __restrict__ tgt,
                                 const float* __restrict__ table,
                                 float* __restrict__ out) {
    int i = blockIdx.x * blockDim.x + threadIdx.x;
    if (i >= TM * BB * EE) return;
    int m = i / EE;
    int e = i % EE;
    int t = m / BB;
    int b = m % BB;
    out[i] = table[(size_t)tgt[b * TT + t] * EE + e];
}

// one launch transposes all 6 recurrent weight matrices (all [3H x H]): Wt[k][n]=W[n][k]
__global__ void transpose_all(const float* __restrict__ w0, const float* __restrict__ w1,
                              const float* __restrict__ w2, const float* __restrict__ w3,
                              const float* __restrict__ w4, const float* __restrict__ w5,
                              float* __restrict__ wt_base) {
    __shared__ float s[32][33];
    const int z = blockIdx.z;
    const float* W = (z == 0) ? w0 : (z == 1) ? w1 : (z == 2) ? w2
                   : (z == 3) ? w3 : (z == 4) ? w4 : w5;
    float* Wt = wt_base + (size_t)z * WT_SZ;
    int n0 = blockIdx.x * 32, k0 = blockIdx.y * 32;
    int tx = threadIdx.x & 31, ty = threadIdx.x >> 5;
#pragma unroll
    for (int i = 0; i < 4; i++)
        s[ty + i * 8][tx] = W[(size_t)(n0 + ty + i * 8) * HH + k0 + tx];
    __syncthreads();
#pragma unroll
    for (int i = 0; i < 4; i++)
        Wt[(size_t)(k0 + ty + i * 8) * H3 + n0 + tx] = s[tx][ty + i * 8];
}

// ---------------- tf32 helpers ----------------
__device__ __forceinline__ uint32_t f2tf(float f) {
    uint32_t u;
    asm("cvt.rna.tf32.f32 %0, %1;" : "=r"(u) : "f"(f));
    return u;
}

// ---------------- tf32 GEMM (batched projections; 128x128, 4 warps) ----------------
// conflict-free [m][36]/[n][36] smem layout (same pattern as gemm_final)
#define MODE_NORM 0
#define MODE_TENC 2   // m = b*64+t -> out row t*32+b (row-major [t][b][n])

template <int MODE>
__global__ void __launch_bounds__(256)
gemm_tf32(const float* __restrict__ A, int lda,
          const float* __restrict__ W, int ldw,
          const float* __restrict__ bias,
          float* __restrict__ C, int M, int N, int K) {
    __shared__ uint32_t As[128 * 36];   // [m][k] stride 36
    __shared__ uint32_t Ws[128 * 36];   // [n][k] stride 36
    const int bm = blockIdx.y * 128, bn = blockIdx.x * 128;
    const int tid = threadIdx.x;
    const int warp = tid >> 5, lane = tid & 31;
    const int wm = (warp & 1) * 64, wn = (warp >> 1) * 32;
    const int g = lane >> 2, tig = lane & 3;
    const int kq = (tid & 7) * 4;

    float acc[4][4][4];
#pragma unroll
    for (int a = 0; a < 4; a++)
#pragma unroll
        for (int b = 0; b < 4; b++)
#pragma unroll
            for (int c = 0; c < 4; c++) acc[a][b][c] = 0.f;

    float4 pa[4], pw[4];

#define G_LD(K0)                                                              \
    _Pragma("unroll") for (int i = 0; i < 4; i++) {                           \
        int e = tid + i * 256;                                                \
        int m = e >> 3;                                                       \
        float4 v = make_float4(0.f, 0.f, 0.f, 0.f);                           \
        if (bm + m < M) v = ld4(A + (size_t)(bm + m) * lda + (K0) + kq);      \
        pa[i] = v;                                                            \
        pw[i] = ld4(W + (size_t)(bn + m) * ldw + (K0) + kq);                  \
    }
#define G_ST()                                                                \
    _Pragma("unroll") for (int i = 0; i < 4; i++) {                           \
        int e = tid + i * 256;                                                \
        int m = e >> 3;                                                       \
        uint4 ua = make_uint4(f2tf(pa[i].x), f2tf(pa[i].y),                   \
                              f2tf(pa[i].z), f2tf(pa[i].w));                  \
        *reinterpret_cast<uint4*>(&As[m * 36 + kq]) = ua;                     \
        uint4 uw = make_uint4(f2tf(pw[i].x), f2tf(pw[i].y),                   \
                              f2tf(pw[i].z), f2tf(pw[i].w));                  \
        *reinterpret_cast<uint4*>(&Ws[m * 36 + kq]) = uw;                     \
    }

    G_LD(0)
    G_ST()
    __syncthreads();

    for (int k0 = 0; k0 < K; k0 += 32) {
        bool has_next = (k0 + 32) < K;
        if (has_next) G_LD(k0 + 32)
#pragma unroll
        for (int kk = 0; kk < 32; kk += 8) {
            uint32_t af[4][4];
#pragma unroll
            for (int mt = 0; mt < 4; mt++) {
                int ml = wm + mt * 16 + g;
                af[mt][0] = As[ml * 36 + kk + tig];
                af[mt][1] = As[(ml + 8) * 36 + kk + tig];
                af[mt][2] = As[ml * 36 + kk + tig + 4];
                af[mt][3] = As[(ml + 8) * 36 + kk + tig + 4];
            }
            uint32_t bf[4][2];
#pragma unroll
            for (int nt = 0; nt < 4; nt++) {
                int nl = wn + nt * 8 + g;
                bf[nt][0] = Ws[nl * 36 + kk + tig];
                bf[nt][1] = Ws[nl * 36 + kk + tig + 4];
            }
#pragma unroll
            for (int mt = 0; mt < 4; mt++)
#pragma unroll
                for (int nt = 0; nt < 4; nt++) {
                    asm volatile(
                        "mma.sync.aligned.m16n8k8.row.col.f32.tf32.tf32.f32 "
                        "{%0,%1,%2,%3}, {%4,%5,%6,%7}, {%8,%9}, {%0,%1,%2,%3};\n"
                        : "+f"(acc[mt][nt][0]), "+f"(acc[mt][nt][1]),
                          "+f"(acc[mt][nt][2]), "+f"(acc[mt][nt][3])
                        : "r"(af[mt][0]), "r"(af[mt][1]), "r"(af[mt][2]), "r"(af[mt][3]),
                          "r"(bf[nt][0]), "r"(bf[nt][1]));
                }
        }
        __syncthreads();
        if (has_next) {
            G_ST()
            __syncthreads();
        }
    }

#pragma unroll
    for (int mt = 0; mt < 4; mt++) {
#pragma unroll
        for (int i2 = 0; i2 < 2; i2++) {
            int m = bm + wm + mt * 16 + g + i2 * 8;
            if (m >= M) continue;
            size_t row;
            if (MODE == MODE_TENC) {
                int t = m & 63, b = m >> 6;
                row = (size_t)(t * BB + b);
            } else {
                row = (size_t)m;
            }
            float* cr = C + row * N;
#pragma unroll
            for (int nt = 0; nt < 4; nt++) {
#pragma unroll
                for (int j = 0; j < 2; j++) {
                    int n = bn + wn + nt * 8 + tig * 2 + j;
                    float v = acc[mt][nt][i2 * 2 + j];
                    if (bias) v += bias[n];
                    cr[n] = v;
                }
            }
        }
    }
#undef G_LD
#undef G_ST
}

// ---------------- final projection: 128x256 tile, 8 warps, m-major grid (R10 proven) ----------------
#define FSM_WORDS (128 * 36 + 256 * 36)
#define FSM_BYTES (FSM_WORDS * 4)

__global__ void __launch_bounds__(256)
gemm_final(const float* __restrict__ A, int lda,
           const float* __restrict__ W, int ldw,
           const float* __restrict__ bias,
           float* __restrict__ C, int M, int N, int K) {
    extern __shared__ uint32_t sm[];
    uint32_t* As = sm;               // [128][36]
    uint32_t* Ws = sm + 128 * 36;    // [256][36]
    const int bm = blockIdx.x * 128;   // m-major: W streams from DRAM once
    const int bn = blockIdx.y * 256;
    const int tid = threadIdx.x;
    const int warp = tid >> 5, lane = tid & 31;
    const int wm = (warp & 1) * 64, wn = (warp >> 1) * 64;
    const int g = lane >> 2, tig = lane & 3;

    float acc[4][8][4];
#pragma unroll
    for (int a = 0; a < 4; a++)
#pragma unroll
        for (int b = 0; b < 8; b++)
#pragma unroll
            for (int c = 0; c < 4; c++) acc[a][b][c] = 0.f;

    const int kq = (tid & 7) * 4;
    float4 pa[4], pw[8];

#define LDA_CHUNK(K0)                                                        \
    _Pragma("unroll") for (int i = 0; i < 4; i++) {                          \
        int e = tid + i * 256;                                               \
        int m = e >> 3;                                                      \
        float4 v = make_float4(0.f, 0.f, 0.f, 0.f);                          \
        if (bm + m < M) v = ld4(A + (size_t)(bm + m) * lda + (K0) + kq);     \
        pa[i] = v;                                                           \
    }
#define LDW_CHUNK(K0)                                                        \
    _Pragma("unroll") for (int i = 0; i < 8; i++) {                          \
        int e = tid + i * 256;                                               \
        int n = e >> 3;                                                      \
        pw[i] = ld4(W + (size_t)(bn + n) * ldw + (K0) + kq);                 \
    }
#define ST_CHUNK()                                                           \
    _Pragma("unroll") for (int i = 0; i < 4; i++) {                          \
        int e = tid + i * 256;                                               \
        int m = e >> 3;                                                      \
        uint4 u = make_uint4(f2tf(pa[i].x), f2tf(pa[i].y),                   \
                             f2tf(pa[i].z), f2tf(pa[i].w));                  \
        *reinterpret_cast<uint4*>(&As[m * 36 + kq]) = u;                     \
    }                                                                        \
    _Pragma("unroll") for (int i = 0; i < 8; i++) {                          \
        int e = tid + i * 256;                                               \
        int n = e >> 3;                                                      \
        uint4 u = make_uint4(f2tf(pw[i].x), f2tf(pw[i].y),                   \
                             f2tf(pw[i].z), f2tf(pw[i].w));                  \
        *reinterpret_cast<uint4*>(&Ws[n * 36 + kq]) = u;                     \
    }

    LDA_CHUNK(0)
    LDW_CHUNK(0)
    ST_CHUNK()
    __syncthreads();

    for (int k0 = 0; k0 < K; k0 += 32) {
        bool has_next = (k0 + 32) < K;
        if (has_next) {
            LDA_CHUNK(k0 + 32)
            LDW_CHUNK(k0 + 32)
        }
#pragma unroll
        for (int kk = 0; kk < 32; kk += 8) {
            uint32_t af[4][4];
#pragma unroll
            for (int mt = 0; mt < 4; mt++) {
                int ml = wm + mt * 16 + g;
                af[mt][0] = As[ml * 36 + kk + tig];
                af[mt][1] = As[(ml + 8) * 36 + kk + tig];
                af[mt][2] = As[ml * 36 + kk + tig + 4];
                af[mt][3] = As[(ml + 8) * 36 + kk + tig + 4];
            }
            uint32_t bf[8][2];
#pragma unroll
            for (int nt = 0; nt < 8; nt++) {
                int nl = wn + nt * 8 + g;
                bf[nt][0] = Ws[nl * 36 + kk + tig];
                bf[nt][1] = Ws[nl * 36 + kk + tig + 4];
            }
#pragma unroll
            for (int mt = 0; mt < 4; mt++)
#pragma unroll
                for (int nt = 0; nt < 8; nt++) {
                    asm volatile(
                        "mma.sync.aligned.m16n8k8.row.col.f32.tf32.tf32.f32 "
                        "{%0,%1,%2,%3}, {%4,%5,%6,%7}, {%8,%9}, {%0,%1,%2,%3};\n"
                        : "+f"(acc[mt][nt][0]), "+f"(acc[mt][nt][1]),
                          "+f"(acc[mt][nt][2]), "+f"(acc[mt][nt][3])
                        : "r"(af[mt][0]), "r"(af[mt][1]), "r"(af[mt][2]), "r"(af[mt][3]),
                          "r"(bf[nt][0]), "r"(bf[nt][1]));
                }
        }
        __syncthreads();
        if (has_next) {
            ST_CHUNK()
            __syncthreads();
        }
    }

    // epilogue: rows m = t*32+b -> out row b*TM + t
#pragma unroll
    for (int mt = 0; mt < 4; mt++) {
#pragma unroll
        for (int i2 = 0; i2 < 2; i2++) {
            int m = bm + wm + mt * 16 + g + i2 * 8;
            if (m >= M) continue;
            int b = m & 31, t = m >> 5;
            float* cr = C + (size_t)(b * TM + t) * N;
#pragma unroll
            for (int nt = 0; nt < 8; nt++) {
#pragma unroll
                for (int j = 0; j < 2; j++) {
                    int n = bn + wn + nt * 8 + tig * 2 + j;
                    cr[n] = acc[mt][nt][i2 * 2 + j] + bias[n];
                }
            }
        }
    }
#undef LDA_CHUNK
#undef LDW_CHUNK
#undef ST_CHUNK
}

// ---------------- tf32 recurrent GEMM body: M=32, n-tile 128, k-chunk 256 ----------------
// At row-major [32][HH] fp32; Wt [k][n] stride H3. Writes slab [b][n] row-major.
__device__ __forceinline__ void rec_mma_body(
    const float* __restrict__ At, const float* __restrict__ Wt,
    float* __restrict__ P,
    uint32_t (*As)[33], uint32_t (*Ws)[132],
    int tid, int n0, int k0) {
    const int warp = tid >> 5, lane = tid & 31;
    const int wn = warp * 16;           // 8 warps x n16
    const int g = lane >> 2, tig = lane & 3;
    const int am = tid >> 3, akq = (tid & 7) * 4;

    float acc[2][2][4];
#pragma unroll
    for (int a = 0; a < 2; a++)
#pragma unroll
        for (int b = 0; b < 2; b++)
#pragma unroll
            for (int c = 0; c < 4; c++) acc[a][b][c] = 0.f;

    float4 pa;
    float4 pw[4];
    pa = ld4(At + (size_t)am * HH + k0 + akq);
#pragma unroll
    for (int i = 0; i < 4; i++) {
        int e = tid + i * 256;
        pw[i] = ld4(Wt + (size_t)(k0 + (e >> 5)) * H3 + n0 + (e & 31) * 4);
    }
    As[akq + 0][am] = f2tf(pa.x); As[akq + 1][am] = f2tf(pa.y);
    As[akq + 2][am] = f2tf(pa.z); As[akq + 3][am] = f2tf(pa.w);
#pragma unroll
    for (int i = 0; i < 4; i++) {
        int e = tid + i * 256;
        uint4 u = make_uint4(f2tf(pw[i].x), f2tf(pw[i].y), f2tf(pw[i].z), f2tf(pw[i].w));
        *reinterpret_cast<uint4*>(&Ws[e >> 5][(e & 31) * 4]) = u;
    }
    __syncthreads();

    for (int c = 0; c < 8; c++) {
        bool has_next = c < 7;
        if (has_next) {
            int kn = k0 + (c + 1) * 32;
            pa = ld4(At + (size_t)am * HH + kn + akq);
#pragma unroll
            for (int i = 0; i < 4; i++) {
                int e = tid + i * 256;
                pw[i] = ld4(Wt + (size_t)(kn + (e >> 5)) * H3 + n0 + (e & 31) * 4);
            }
        }
#pragma unroll
        for (int kk = 0; kk < 32; kk += 8) {
            uint32_t af[2][4];
#pragma unroll
            for (int mt = 0; mt < 2; mt++) {
                int ml = mt * 16 + g;
                af[mt][0] = As[kk + tig][ml];
                af[mt][1] = As[kk + tig][ml + 8];
                af[mt][2] = As[kk + tig + 4][ml];
                af[mt][3] = As[kk + tig + 4][ml + 8];
            }
            uint32_t bf[2][2];
#pragma unroll
            for (int nt = 0; nt < 2; nt++) {
                int nl = wn + nt * 8 + g;
                bf[nt][0] = Ws[kk + tig][nl];
                bf[nt][1] = Ws[kk + tig + 4][nl];
            }
#pragma unroll
            for (int mt = 0; mt < 2; mt++)
#pragma unroll
                for (int nt = 0; nt < 2; nt++) {
                    asm volatile(
                        "mma.sync.aligned.m16n8k8.row.col.f32.tf32.tf32.f32 "
                        "{%0,%1,%2,%3}, {%4,%5,%6,%7}, {%8,%9}, {%0,%1,%2,%3};\n"
                        : "+f"(acc[mt][nt][0]), "+f"(acc[mt][nt][1]),
                          "+f"(acc[mt][nt][2]), "+f"(acc[mt][nt][3])
                        : "r"(af[mt][0]), "r"(af[mt][1]), "r"(af[mt][2]), "r"(af[mt][3]),
                          "r"(bf[nt][0]), "r"(bf[nt][1]));
                }
        }
        __syncthreads();
        if (has_next) {
            As[akq + 0][am] = f2tf(pa.x); As[akq + 1][am] = f2tf(pa.y);
            As[akq + 2][am] = f2tf(pa.z); As[akq + 3][am] = f2tf(pa.w);
#pragma unroll
            for (int i = 0; i < 4; i++) {
                int e = tid + i * 256;
                uint4 u = make_uint4(f2tf(pw[i].x), f2tf(pw[i].y),
                                     f2tf(pw[i].z), f2tf(pw[i].w));
                *reinterpret_cast<uint4*>(&Ws[e >> 5][(e & 31) * 4]) = u;
            }
            __syncthreads();
        }
    }

    // epilogue: acc rows -> slab [b][n]
#pragma unroll
    for (int mt = 0; mt < 2; mt++) {
#pragma unroll
        for (int i2 = 0; i2 < 2; i2++) {
            int b = mt * 16 + g + i2 * 8;
            float* pr = P + (size_t)b * H3 + n0 + wn;
#pragma unroll
            for (int nt = 0; nt < 2; nt++) {
#pragma unroll
                for (int j = 0; j < 2; j++)
                    pr[nt * 8 + tig * 2 + j] = acc[mt][nt][i2 * 2 + j];
            }
        }
    }
}

// encoder wavefront rec: z0 h0@ewhh0 (slabs0-3), z1 h0@ewih1 (4-7), z2 h1@ewhh1 (8-11)
__global__ void __launch_bounds__(256)
enc_rec(const float* __restrict__ h0c, const float* __restrict__ h1c,
        const float* __restrict__ wt_whh0, const float* __restrict__ wt_wih1,
        const float* __restrict__ wt_whh1, float* __restrict__ part) {
    __shared__ uint32_t As[32][33];
    __shared__ uint32_t Ws[32][132];
    const int z = blockIdx.z;
    const float* A = (z == 2) ? h1c : h0c;
    const float* W = (z == 0) ? wt_whh0 : (z == 1) ? wt_wih1 : wt_whh1;
    rec_mma_body(A, W, part + (size_t)(z * KSPLIT + blockIdx.y) * PARTSZ,
                 As, Ws, threadIdx.x, blockIdx.x * 128, blockIdx.y * 256);
}

// encoder wavefront gate: blocks 0-127 layer0 (t0), 128-255 layer1 (t1)
__global__ void __launch_bounds__(256)
enc_gate(const float* __restrict__ part,
         const float* __restrict__ gi0,      // [t][b][n]
         const float* __restrict__ bhh0, const float* __restrict__ bih1,
         const float* __restrict__ bhh1,
         const float* __restrict__ h0c, float* __restrict__ h0n,
         const float* __restrict__ h1c, float* __restrict__ h1n,
         float* __restrict__ encout,
         int t0, int t0v, int t1, int t1v) {
    const int lay = blockIdx.x >> 7;
    const int lb = blockIdx.x & 127;
    const int b = lb >> 2;
    const int h = (lb & 3) * 256 + threadIdx.x;
    if (lay == 0) {
        if (!t0v) return;
        const float* G = gi0 + ((size_t)t0 * BB + b) * H3;
        float gr = G[h], gz = G[HH + h], gn = G[2 * HH + h];
        float hr = bhh0[h], hz = bhh0[HH + h], hn = bhh0[2 * HH + h];
#pragma unroll
        for (int j = 0; j < KSPLIT; j++) {
            const float* P = part + (size_t)j * PARTSZ + (size_t)b * H3;
            hr += P[h]; hz += P[HH + h]; hn += P[2 * HH + h];
        }
        float r = 1.f / (1.f + expf(-(gr + hr)));
        float z = 1.f / (1.f + expf(-(gz + hz)));
        float n = tanhf(gn + r * hn);
        float hp = h0c[(size_t)b * HH + h];
        h0n[(size_t)b * HH + h] = (1.f - z) * n + z * hp;
    } else {
        if (!t1v) return;
        float gr = bih1[h], gz = bih1[HH + h], gn = bih1[2 * HH + h];
        float hr = bhh1[h], hz = bhh1[HH + h], hn = bhh1[2 * HH + h];
#pragma unroll
        for (int j = 0; j < KSPLIT; j++) {
            const float* Px = part + (size_t)(KSPLIT + j) * PARTSZ + (size_t)b * H3;
            const float* Ph = part + (size_t)(2 * KSPLIT + j) * PARTSZ + (size_t)b * H3;
            gr += Px[h]; gz += Px[HH + h]; gn += Px[2 * HH + h];
            hr += Ph[h]; hz += Ph[HH + h]; hn += Ph[2 * HH + h];
        }
        float r = 1.f / (1.f + expf(-(gr + hr)));
        float z = 1.f / (1.f + expf(-(gz + hz)));
        float n = tanhf(gn + r * hn);
        float hp = h1c[(size_t)b * HH + h];
        float out = (1.f - z) * n + z * hp;
        h1n[(size_t)b * HH + h] = out;
        encout[((size_t)b * SS + t1) * HH + h] = out;
    }
}

// decoder launch A: blocks 0-31 attention; 32+: rec z0 h0@dwhh0 (slabs0-3), z1 h1@dwhh1 (4-7)
__global__ void __launch_bounds__(256)
dec_A(const float* __restrict__ proj, const float* __restrict__ d1,
      const int* __restrict__ src_ids, float* __restrict__ attw,
      const float* __restrict__ h0c, const float* __restrict__ h1c,
      const float* __restrict__ wt_whh0, const float* __restrict__ wt_whh1,
      float* __restrict__ part) {
    __shared__ uint32_t As[32][33];
    __shared__ uint32_t Ws[32][132];
    const int bid = blockIdx.x;
    const int tid = threadIdx.x;
    if (bid < 32) {
        float* sc = reinterpret_cast<float*>(Ws);
        const int b = bid;
        const int lane = tid & 31, warp = tid >> 5;
        const float* d1b = d1 + (size_t)b * HH;
        for (int s = warp; s < SS; s += 8) {
            const float* pr = proj + ((size_t)b * SS + s) * HH;
            float p = 0.f;
#pragma unroll
            for (int j = 0; j < 8; j++) {
                int k0 = j * 128 + lane * 4;
                float4 dv = ld4(d1b + k0);
                float4 pv = ld4(pr + k0);
                p += dv.x * pv.x + dv.y * pv.y + dv.z * pv.z + dv.w * pv.w;
            }
#pragma unroll
            for (int o = 16; o; o >>= 1) p += __shfl_xor_sync(0xffffffffu, p, o);
            if (lane == 0) sc[s] = (src_ids[b * SS + s] != 0) ? p : -1e9f;
        }
        __syncthreads();
        if (warp == 0) {
            float v0 = sc[lane], v1 = sc[lane + 32];
            float m = fmaxf(v0, v1);
#pragma unroll
            for (int o = 16; o; o >>= 1) m = fmaxf(m, __shfl_xor_sync(0xffffffffu, m, o));
            float e0 = expf(v0 - m), e1 = expf(v1 - m);
            float su = e0 + e1;
#pragma unroll
            for (int o = 16; o; o >>= 1) su += __shfl_xor_sync(0xffffffffu, su, o);
            attw[b * SS + lane] = e0 / su;
            attw[b * SS + lane + 32] = e1 / su;
        }
    } else {
        const int e = bid - 32;          // 0..191
        const int z = e / 96;            // 0: h0@whh0, 1: h1@whh1
        const int r = e % 96;
        const int n0 = (r % 24) * 128;
        const int kc = r / 24;           // 0..3
        const float* A = z ? h1c : h0c;
        const float* W = z ? wt_whh1 : wt_whh0;
        rec_mma_body(A, W, part + (size_t)(z * KSPLIT + kc) * PARTSZ,
                     As, Ws, tid, n0, kc * 256);
    }
}

// decoder gate0: gi = epre + Σ_s attw*encV ; h-side = slabs 0-3
__global__ void __launch_bounds__(256)
dec_gate0(const float* __restrict__ part,
          const float* __restrict__ epre_t,   // [b][n]
          const float* __restrict__ encV,     // [b][s][n]
          const float* __restrict__ attw,
          const float* __restrict__ bhh0,
          const float* __restrict__ h0c, float* __restrict__ h0n) {
    __shared__ float aw[SS];
    const int b = blockIdx.x >> 2;
    const int h = (blockIdx.x & 3) * 256 + threadIdx.x;
    if (threadIdx.x < SS) aw[threadIdx.x] = attw[b * SS + threadIdx.x];
    __syncthreads();
    const float* G = epre_t + (size_t)b * H3;
    float gr = G[h], gz = G[HH + h], gn = G[2 * HH + h];
    const float* V = encV + (size_t)b * SS * H3;
#pragma unroll 4
    for (int s = 0; s < SS; s++) {
        float w = aw[s];
        const float* vr = V + (size_t)s * H3;
        gr += w * vr[h];
        gz += w * vr[HH + h];
        gn += w * vr[2 * HH + h];
    }
    float hr = bhh0[h], hz = bhh0[HH + h], hn = bhh0[2 * HH + h];
#pragma unroll
    for (int j = 0; j < KSPLIT; j++) {
        const float* P = part + (size_t)j * PARTSZ + (size_t)b * H3;
        hr += P[h]; hz += P[HH + h]; hn += P[2 * HH + h];
    }
    float r = 1.f / (1.f + expf(-(gr + hr)));
    float z = 1.f / (1.f + expf(-(gz + hz)));
    float n = tanhf(gn + r * hn);
    float hp = h0c[(size_t)b * HH + h];
    h0n[(size_t)b * HH + h] = (1.f - z) * n + z * hp;
}

// decoder launch C: rec h0'@dwih1 -> slabs 8-11
__global__ void __launch_bounds__(256)
dec_C(const float* __restrict__ h0n, const float* __restrict__ wt_wih1,
      float* __restrict__ part) {
    __shared__ uint32_t As[32][33];
    __shared__ uint32_t Ws[32][132];
    rec_mma_body(h0n, wt_wih1, part + (size_t)(2 * KSPLIT + blockIdx.y) * PARTSZ,
                 As, Ws, threadIdx.x, blockIdx.x * 128, blockIdx.y * 256);
}

// decoder gate1: x = slabs 8-11 + bih1; h = slabs 4-7 + bhh1; writes h1', cat [d1|ctx]
__global__ void __launch_bounds__(256)
dec_gate1(const float* __restrict__ part,
          const float* __restrict__ bih1, const float* __restrict__ bhh1,
          const float* __restrict__ encout,   // [b][s][h]
          const float* __restrict__ attw,
          const float* __restrict__ h1c, float* __restrict__ h1n,
          float* __restrict__ cat_t) {
    __shared__ float aw[SS];
    const int b = blockIdx.x >> 2;
    const int h = (blockIdx.x & 3) * 256 + threadIdx.x;
    if (threadIdx.x < SS) aw[threadIdx.x] = attw[b * SS + threadIdx.x];
    __syncthreads();
    float gr = bih1[h], gz = bih1[HH + h], gn = bih1[2 * HH + h];
    float hr = bhh1[h], hz = bhh1[HH + h], hn = bhh1[2 * HH + h];
#pragma unroll
    for (int j = 0; j < KSPLIT; j++) {
        const float* Px = part + (size_t)(2 * KSPLIT + j) * PARTSZ + (size_t)b * H3;
        const float* Ph = part + (size_t)(KSPLIT + j) * PARTSZ + (size_t)b * H3;
        gr += Px[h]; gz += Px[HH + h]; gn += Px[2 * HH + h];
        hr += Ph[h]; hz += Ph[HH + h]; hn += Ph[2 * HH + h];
    }
    float r = 1.f / (1.f + expf(-(gr + hr)));
    float z = 1.f / (1.f + expf(-(gz + hz)));
    float n = tanhf(gn + r * hn);
    float hp = h1c[(size_t)b * HH + h];
    float out = (1.f - z) * n + z * hp;
    h1n[(size_t)b * HH + h] = out;
    cat_t[(size_t)b * H2 + h] = out;
    const float* E = encout + (size_t)b * SS * HH;
    float c = 0.f;
#pragma unroll 8
    for (int s = 0; s < SS; s++) c += aw[s] * E[(size_t)s * HH + h];
    cat_t[(size_t)b * H2 + HH + h] = c;
}

// ---------------- host launcher ----------------
extern "C" void kernel_launch(void* const* d_in, const int* in_sizes, int n_in,
                              void* d_out, int out_size) {
    const int*   src_ids  = (const int*)d_in[0];
    const int*   tgt_ids  = (const int*)d_in[2];
    const float* enc_emb  = (const float*)d_in[3];
    const float* dec_emb  = (const float*)d_in[4];
    const float* enc_wih0 = (const float*)d_in[5];
    const float* enc_whh0 = (const float*)d_in[6];
    const float* enc_bih0 = (const float*)d_in[7];
    const float* enc_bhh0 = (const float*)d_in[8];
    const float* enc_wih1 = (const float*)d_in[9];
    const float* enc_whh1 = (const float*)d_in[10];
    const float* enc_bih1 = (const float*)d_in[11];
    const float* enc_bhh1 = (const float*)d_in[12];
    const float* dec_wih0 = (const float*)d_in[13];
    const float* dec_whh0 = (const float*)d_in[14];
    const float* dec_bih0 = (const float*)d_in[15];
    const float* dec_bhh0 = (const float*)d_in[16];
    const float* dec_wih1 = (const float*)d_in[17];
    const float* dec_whh1 = (const float*)d_in[18];
    const float* dec_bih1 = (const float*)d_in[19];
    const float* dec_bhh1 = (const float*)d_in[20];
    const float* attn_w   = (const float*)d_in[21];
    const float* out_w    = (const float*)d_in[22];
    const float* out_b    = (const float*)d_in[23];
    float* out = (float*)d_out;

    float* base = nullptr;
    cudaGetSymbolAddress((void**)&base, g_scratch);
    float* embS   = base + OFF_EMBS;
    float* gi0    = base + OFF_GI0;
    float* encout = base + OFF_ENCOUT;
    float* proj   = base + OFF_PROJ;
    float* encV   = base + OFF_ENCV;
    float* embT   = base + OFF_EMBT;
    float* epre   = base + OFF_EPRE;
    float* cat    = base + OFF_CAT;
    float* h0A    = base + OFF_H0A;
    float* h0B    = base + OFF_H0B;
    float* h1A    = base + OFF_H1A;
    float* h1B    = base + OFF_H1B;
    float* attw   = base + OFF_ATTW;
    float* part   = base + OFF_PART;
    float* wt_ewhh0 = base + OFF_WT + 0 * WT_SZ;
    float* wt_ewhh1 = base + OFF_WT + 1 * WT_SZ;
    float* wt_ewih1 = base + OFF_WT + 2 * WT_SZ;
    float* wt_dwhh0 = base + OFF_WT + 3 * WT_SZ;
    float* wt_dwhh1 = base + OFF_WT + 4 * WT_SZ;
    float* wt_dwih1 = base + OFF_WT + 5 * WT_SZ;

    cudaFuncSetAttribute(gemm_final, cudaFuncAttributeMaxDynamicSharedMemorySize, FSM_BYTES);

    transpose_all<<<dim3(H3 / 32, HH / 32, 6), 256>>>(
        enc_whh0, enc_whh1, enc_wih1, dec_whh0, dec_whh1, dec_wih1, base + OFF_WT);
    embed_enc_kernel<<<(BB * SS * EE + 255) / 256, 256>>>(src_ids, enc_emb, embS);
    embed_dec_kernel<<<(TM * BB * EE + 255) / 256, 256>>>(tgt_ids, dec_emb, embT);
    gemm_tf32<MODE_TENC><<<dim3(H3 / 128, 16), 256>>>(
        embS, EE, enc_wih0, EE, enc_bih0, gi0, BB * SS, H3, EE);
    zero_kernel<<<(4 * BB * HH + 255) / 256, 256>>>(h0A, 4 * BB * HH);
    // epre = embT @ dec_wih0[:, :E]^T + dec_bih0 -> [t][b][n]
    gemm_tf32<MODE_NORM><<<dim3(H3 / 128, (TM * BB + 127) / 128), 256>>>(
        embT, EE, dec_wih0, EE + HH, dec_bih0, epre, TM * BB, H3, EE);

    float* h0_cur = h0A; float* h0_nxt = h0B;
    float* h1_cur = h1A; float* h1_nxt = h1B;

    // ---- encoder wavefront: 65 stages, 2 launches each ----
    for (int s = 0; s <= SS; s++) {
        enc_rec<<<dim3(24, KSPLIT, 3), 256>>>(h0_cur, h1_cur,
                                              wt_ewhh0, wt_ewih1, wt_ewhh1, part);
        enc_gate<<<256, 256>>>(part, gi0, enc_bhh0, enc_bih1, enc_bhh1,
                               h0_cur, h0_nxt, h1_cur, h1_nxt, encout,
                               s, (s < SS) ? 1 : 0, s - 1, (s > 0) ? 1 : 0);
        if (s < SS) { float* tmp = h0_cur; h0_cur = h0_nxt; h0_nxt = tmp; }
        if (s > 0)  { float* tmp = h1_cur; h1_cur = h1_nxt; h1_nxt = tmp; }
    }

    // proj = encout @ attn_w^T ; encV = encout @ dec_wih0[:, E:]^T
    gemm_tf32<MODE_NORM><<<dim3(HH / 128, 16), 256>>>(
        encout, HH, attn_w, HH, nullptr, proj, BB * SS, HH, HH);
    gemm_tf32<MODE_NORM><<<dim3(H3 / 128, 16), 256>>>(
        encout, HH, dec_wih0 + EE, EE + HH, nullptr, encV, BB * SS, H3, HH);

    // ---- decoder loop: 4 launches per step ----
    for (int t = 0; t < TM; t++) {
        float* epre_t = epre + (size_t)t * BB * H3;
        float* cat_t  = cat + (size_t)t * BB * H2;
        dec_A<<<32 + 2 * 96, 256>>>(proj, h1_cur, src_ids, attw,
                                    h0_cur, h1_cur, wt_dwhh0, wt_dwhh1, part);
        dec_gate0<<<128, 256>>>(part, epre_t, encV, attw, dec_bhh0, h0_cur, h0_nxt);
        dec_C<<<dim3(24, KSPLIT), 256>>>(h0_nxt, wt_dwih1, part);
        dec_gate1<<<128, 256>>>(part, dec_bih1, dec_bhh1, encout, attw,
                                h1_cur, h1_nxt, cat_t);
        float* tmp;
        tmp = h0_cur; h0_cur = h0_nxt; h0_nxt = tmp;
        tmp = h1_cur; h1_cur = h1_nxt; h1_nxt = tmp;
    }

    // ---- final projection: logits = cat @ out_w^T + out_b -> (B, TM, V) ----
    gemm_final<<<dim3((TM * BB + 127) / 128, VV / 256), 256, FSM_BYTES>>>(
        cat, H2, out_w, H2, out_b, out, TM * BB, VV, H2);
}

// round 14
// speedup vs baseline: 1.0382x; 1.0374x over previous
#include <cuda_runtime.h>
#include <cstdint>

// Problem dims
#define BB 32
#define SS 64
#define TT 48
#define TM 47      // T-1 decoder steps
#define VV 32000
#define EE 512
#define HH 1024
#define H3 3072
#define H2 2048
#define KSPLIT 4
#define PARTSZ ((size_t)BB * H3)

// ---------------- scratch (device global, no allocs) ----------------
#define OFF_EMBS   0ull                                   // [b][s][e]
#define OFF_GI0    (OFF_EMBS   + (size_t)BB*SS*EE)        // [t][b][n]
#define OFF_ENCOUT (OFF_GI0    + (size_t)BB*SS*H3)        // [b][t][h]
#define OFF_PROJ   (OFF_ENCOUT + (size_t)BB*SS*HH)        // [b][s][h]
#define OFF_ENCV   (OFF_PROJ   + (size_t)BB*SS*HH)        // [b][s][n]  encout @ Wc^T
#define OFF_EMBT   (OFF_ENCV   + (size_t)BB*SS*H3)        // rows m=t*B+b
#define OFF_EPRE   (OFF_EMBT   + (size_t)TM*BB*EE)        // [t][b][n]
#define OFF_CAT    (OFF_EPRE   + (size_t)TM*BB*H3)        // rows m=t*B+b, [d1|ctx]
#define OFF_H0A    (OFF_CAT    + (size_t)TM*BB*H2)        // state [b][h] row-major
#define OFF_H0B    (OFF_H0A    + (size_t)BB*HH)
#define OFF_H1A    (OFF_H0B    + (size_t)BB*HH)
#define OFF_H1B    (OFF_H1A    + (size_t)BB*HH)
#define OFF_ATTW   (OFF_H1B    + (size_t)BB*HH)           // attn weights [b][64]
#define OFF_PART   (OFF_ATTW   + (size_t)BB*SS)           // 12 partial slabs [b][n]
#define OFF_WT     (OFF_PART   + 12*PARTSZ)               // 6 transposed weights [k][n]
#define WT_SZ      ((size_t)HH * H3)
#define SCRATCH_TOTAL (OFF_WT + 6*WT_SZ)

__device__ float g_scratch[SCRATCH_TOTAL];

// ---------------- small helpers ----------------
__device__ __forceinline__ float4 ld4(const float* p) {
    return *reinterpret_cast<const float4*>(p);
}
__device__ __forceinline__ void st4(float* p, float4 v) {
    *reinterpret_cast<float4*>(p) = v;
}
__device__ __forceinline__ uint32_t s2u(const void* p) {
    return (uint32_t)__cvta_generic_to_shared(p);
}
__device__ __forceinline__ void ldsm4(uint32_t* r, uint32_t a) {
    asm volatile("ldmatrix.sync.aligned.m8n8.x4.shared.b16 {%0,%1,%2,%3}, [%4];"
                 : "=r"(r[0]), "=r"(r[1]), "=r"(r[2]), "=r"(r[3]) : "r"(a));
}

__global__ void zero_kernel(float* p, int n) {
    int i = blockIdx.x * blockDim.x + threadIdx.x;
    if (i < n) p[i] = 0.f;
}

__global__ void embed_enc_kernel(const int* __restrict__ ids,
                                 const float* __restrict__ table,
                                 float* __restrict__ out) {
    int i = blockIdx.x * blockDim.x + threadIdx.x;
    if (i >= BB * SS * EE) return;
    int tok = i / EE;
    int e = i % EE;
    out[i] = table[(size_t)ids[tok] * EE + e];
}

__global__ void embed_dec_kernel(const int* __restrict__ tgt,
                                 const float* __restrict__ table,
                                 float* __restrict__ out) {
    int i = blockIdx.x * blockDim.x + threadIdx.x;
    if (i >= TM * BB * EE) return;
    int m = i / EE;
    int e = i % EE;
    int t = m / BB;
    int b = m % BB;
    out[i] = table[(size_t)tgt[b * TT + t] * EE + e];
}

// one launch transposes all 6 recurrent weight matrices (all [3H x H]): Wt[k][n]=W[n][k]
__global__ void transpose_all(const float* __restrict__ w0, const float* __restrict__ w1,
                              const float* __restrict__ w2, const float* __restrict__ w3,
                              const float* __restrict__ w4, const float* __restrict__ w5,
                              float* __restrict__ wt_base) {
    __shared__ float s[32][33];
    const int z = blockIdx.z;
    const float* W = (z == 0) ? w0 : (z == 1) ? w1 : (z == 2) ? w2
                   : (z == 3) ? w3 : (z == 4) ? w4 : w5;
    float* Wt = wt_base + (size_t)z * WT_SZ;
    int n0 = blockIdx.x * 32, k0 = blockIdx.y * 32;
    int tx = threadIdx.x & 31, ty = threadIdx.x >> 5;
#pragma unroll
    for (int i = 0; i < 4; i++)
        s[ty + i * 8][tx] = W[(size_t)(n0 + ty + i * 8) * HH + k0 + tx];
    __syncthreads();
#pragma unroll
    for (int i = 0; i < 4; i++)
        Wt[(size_t)(k0 + ty + i * 8) * H3 + n0 + tx] = s[tx][ty + i * 8];
}

// ---------------- tf32 helpers ----------------
__device__ __forceinline__ uint32_t f2tf(float f) {
    uint32_t u;
    asm("cvt.rna.tf32.f32 %0, %1;" : "=r"(u) : "f"(f));
    return u;
}

// ---------------- tf32 GEMM (batched projections; 128x128, 4 warps, ldmatrix) ----------------
#define MODE_NORM 0
#define MODE_TENC 2   // m = b*64+t -> out row t*32+b (row-major [t][b][n])

template <int MODE>
__global__ void __launch_bounds__(256)
gemm_tf32(const float* __restrict__ A, int lda,
          const float* __restrict__ W, int ldw,
          const float* __restrict__ bias,
          float* __restrict__ C, int M, int N, int K) {
    __shared__ uint32_t As[128 * 36];   // [m][k] stride 36
    __shared__ uint32_t Ws[128 * 36];   // [n][k] stride 36
    const int bm = blockIdx.y * 128, bn = blockIdx.x * 128;
    const int tid = threadIdx.x;
    const int warp = tid >> 5, lane = tid & 31;
    const int wm = (warp & 1) * 64, wn = (warp >> 1) * 32;
    const int g = lane >> 2, tig = lane & 3;
    const int kq = (tid & 7) * 4;

    // ldmatrix per-lane source rows/cols
    const int arow = (lane & 7) + ((lane >> 3) & 1) * 8;
    const int acol = ((lane >> 4) & 1) * 4;
    const int brow = (lane & 7) + ((lane >> 4) & 1) * 8;
    const int bcol = ((lane >> 3) & 1) * 4;
    uint32_t aA[4], bA[2];
#pragma unroll
    for (int mt = 0; mt < 4; mt++)
        aA[mt] = s2u(&As[(wm + mt * 16 + arow) * 36 + acol]);
#pragma unroll
    for (int p = 0; p < 2; p++)
        bA[p] = s2u(&Ws[(wn + p * 16 + brow) * 36 + bcol]);

    float acc[4][4][4];
#pragma unroll
    for (int a = 0; a < 4; a++)
#pragma unroll
        for (int b = 0; b < 4; b++)
#pragma unroll
            for (int c = 0; c < 4; c++) acc[a][b][c] = 0.f;

    float4 pa[4], pw[4];

#define G_LD(K0)                                                              \
    _Pragma("unroll") for (int i = 0; i < 4; i++) {                           \
        int e = tid + i * 256;                                                \
        int m = e >> 3;                                                       \
        float4 v = make_float4(0.f, 0.f, 0.f, 0.f);                           \
        if (bm + m < M) v = ld4(A + (size_t)(bm + m) * lda + (K0) + kq);      \
        pa[i] = v;                                                            \
        pw[i] = ld4(W + (size_t)(bn + m) * ldw + (K0) + kq);                  \
    }
#define G_ST()                                                                \
    _Pragma("unroll") for (int i = 0; i < 4; i++) {                           \
        int e = tid + i * 256;                                                \
        int m = e >> 3;                                                       \
        uint4 ua = make_uint4(f2tf(pa[i].x), f2tf(pa[i].y),                   \
                              f2tf(pa[i].z), f2tf(pa[i].w));                  \
        *reinterpret_cast<uint4*>(&As[m * 36 + kq]) = ua;                     \
        uint4 uw = make_uint4(f2tf(pw[i].x), f2tf(pw[i].y),                   \
                              f2tf(pw[i].z), f2tf(pw[i].w));                  \
        *reinterpret_cast<uint4*>(&Ws[m * 36 + kq]) = uw;                     \
    }

    G_LD(0)
    G_ST()
    __syncthreads();

    for (int k0 = 0; k0 < K; k0 += 32) {
        bool has_next = (k0 + 32) < K;
        if (has_next) G_LD(k0 + 32)
#pragma unroll
        for (int kk = 0; kk < 32; kk += 8) {
            uint32_t af[4][4];
#pragma unroll
            for (int mt = 0; mt < 4; mt++)
                ldsm4(af[mt], aA[mt] + kk * 4);
            uint32_t bq[2][4];
#pragma unroll
            for (int p = 0; p < 2; p++)
                ldsm4(bq[p], bA[p] + kk * 4);
#pragma unroll
            for (int mt = 0; mt < 4; mt++)
#pragma unroll
                for (int nt = 0; nt < 4; nt++) {
                    asm volatile(
                        "mma.sync.aligned.m16n8k8.row.col.f32.tf32.tf32.f32 "
                        "{%0,%1,%2,%3}, {%4,%5,%6,%7}, {%8,%9}, {%0,%1,%2,%3};\n"
                        : "+f"(acc[mt][nt][0]), "+f"(acc[mt][nt][1]),
                          "+f"(acc[mt][nt][2]), "+f"(acc[mt][nt][3])
                        : "r"(af[mt][0]), "r"(af[mt][1]), "r"(af[mt][2]), "r"(af[mt][3]),
                          "r"(bq[nt >> 1][(nt & 1) * 2]), "r"(bq[nt >> 1][(nt & 1) * 2 + 1]));
                }
        }
        __syncthreads();
        if (has_next) {
            G_ST()
            __syncthreads();
        }
    }

#pragma unroll
    for (int mt = 0; mt < 4; mt++) {
#pragma unroll
        for (int i2 = 0; i2 < 2; i2++) {
            int m = bm + wm + mt * 16 + g + i2 * 8;
            if (m >= M) continue;
            size_t row;
            if (MODE == MODE_TENC) {
                int t = m & 63, b = m >> 6;
                row = (size_t)(t * BB + b);
            } else {
                row = (size_t)m;
            }
            float* cr = C + row * N;
#pragma unroll
            for (int nt = 0; nt < 4; nt++) {
#pragma unroll
                for (int j = 0; j < 2; j++) {
                    int n = bn + wn + nt * 8 + tig * 2 + j;
                    float v = acc[mt][nt][i2 * 2 + j];
                    if (bias) v += bias[n];
                    cr[n] = v;
                }
            }
        }
    }
#undef G_LD
#undef G_ST
}

// ---------------- final projection: 128x256 tile, 8 warps, m-major, ldmatrix ----------------
#define FSM_WORDS (128 * 36 + 256 * 36)
#define FSM_BYTES (FSM_WORDS * 4)

__global__ void __launch_bounds__(256)
gemm_final(const float* __restrict__ A, int lda,
           const float* __restrict__ W, int ldw,
           const float* __restrict__ bias,
           float* __restrict__ C, int M, int N, int K) {
    extern __shared__ uint32_t sm[];
    uint32_t* As = sm;               // [128][36]
    uint32_t* Ws = sm + 128 * 36;    // [256][36]
    const int bm = blockIdx.x * 128;   // m-major: W streams from DRAM once
    const int bn = blockIdx.y * 256;
    const int tid = threadIdx.x;
    const int warp = tid >> 5, lane = tid & 31;
    const int wm = (warp & 1) * 64, wn = (warp >> 1) * 64;
    const int g = lane >> 2, tig = lane & 3;
    const int kq = (tid & 7) * 4;

    const int arow = (lane & 7) + ((lane >> 3) & 1) * 8;
    const int acol = ((lane >> 4) & 1) * 4;
    const int brow = (lane & 7) + ((lane >> 4) & 1) * 8;
    const int bcol = ((lane >> 3) & 1) * 4;
    uint32_t aA[4], bA[4];
#pragma unroll
    for (int mt = 0; mt < 4; mt++)
        aA[mt] = s2u(&As[(wm + mt * 16 + arow) * 36 + acol]);
#pragma unroll
    for (int p = 0; p < 4; p++)
        bA[p] = s2u(&Ws[(wn + p * 16 + brow) * 36 + bcol]);

    float acc[4][8][4];
#pragma unroll
    for (int a = 0; a < 4; a++)
#pragma unroll
        for (int b = 0; b < 8; b++)
#pragma unroll
            for (int c = 0; c < 4; c++) acc[a][b][c] = 0.f;

    float4 pa[4], pw[8];

#define LDA_CHUNK(K0)                                                        \
    _Pragma("unroll") for (int i = 0; i < 4; i++) {                          \
        int e = tid + i * 256;                                               \
        int m = e >> 3;                                                      \
        float4 v = make_float4(0.f, 0.f, 0.f, 0.f);                          \
        if (bm + m < M) v = ld4(A + (size_t)(bm + m) * lda + (K0) + kq);     \
        pa[i] = v;                                                           \
    }
#define LDW_CHUNK(K0)                                                        \
    _Pragma("unroll") for (int i = 0; i < 8; i++) {                          \
        int e = tid + i * 256;                                               \
        int n = e >> 3;                                                      \
        pw[i] = ld4(W + (size_t)(bn + n) * ldw + (K0) + kq);                 \
    }
#define ST_CHUNK()                                                           \
    _Pragma("unroll") for (int i = 0; i < 4; i++) {                          \
        int e = tid + i * 256;                                               \
        int m = e >> 3;                                                      \
        uint4 u = make_uint4(f2tf(pa[i].x), f2tf(pa[i].y),                   \
                             f2tf(pa[i].z), f2tf(pa[i].w));                  \
        *reinterpret_cast<uint4*>(&As[m * 36 + kq]) = u;                     \
    }                                                                        \
    _Pragma("unroll") for (int i = 0; i < 8; i++) {                          \
        int e = tid + i * 256;                                               \
        int n = e >> 3;                                                      \
        uint4 u = make_uint4(f2tf(pw[i].x), f2tf(pw[i].y),                   \
                             f2tf(pw[i].z), f2tf(pw[i].w));                  \
        *reinterpret_cast<uint4*>(&Ws[n * 36 + kq]) = u;                     \
    }

    LDA_CHUNK(0)
    LDW_CHUNK(0)
    ST_CHUNK()
    __syncthreads();

    for (int k0 = 0; k0 < K; k0 += 32) {
        bool has_next = (k0 + 32) < K;
        if (has_next) {
            LDA_CHUNK(k0 + 32)
            LDW_CHUNK(k0 + 32)
        }
#pragma unroll
        for (int kk = 0; kk < 32; kk += 8) {
            uint32_t af[4][4];
#pragma unroll
            for (int mt = 0; mt < 4; mt++)
                ldsm4(af[mt], aA[mt] + kk * 4);
            uint32_t bq[4][4];
#pragma unroll
            for (int p = 0; p < 4; p++)
                ldsm4(bq[p], bA[p] + kk * 4);
#pragma unroll
            for (int mt = 0; mt < 4; mt++)
#pragma unroll
                for (int nt = 0; nt < 8; nt++) {
                    asm volatile(
                        "mma.sync.aligned.m16n8k8.row.col.f32.tf32.tf32.f32 "
                        "{%0,%1,%2,%3}, {%4,%5,%6,%7}, {%8,%9}, {%0,%1,%2,%3};\n"
                        : "+f"(acc[mt][nt][0]), "+f"(acc[mt][nt][1]),
                          "+f"(acc[mt][nt][2]), "+f"(acc[mt][nt][3])
                        : "r"(af[mt][0]), "r"(af[mt][1]), "r"(af[mt][2]), "r"(af[mt][3]),
                          "r"(bq[nt >> 1][(nt & 1) * 2]), "r"(bq[nt >> 1][(nt & 1) * 2 + 1]));
                }
        }
        __syncthreads();
        if (has_next) {
            ST_CHUNK()
            __syncthreads();
        }
    }

    // epilogue: rows m = t*32+b -> out row b*TM + t
#pragma unroll
    for (int mt = 0; mt < 4; mt++) {
#pragma unroll
        for (int i2 = 0; i2 < 2; i2++) {
            int m = bm + wm + mt * 16 + g + i2 * 8;
            if (m >= M) continue;
            int b = m & 31, t = m >> 5;
            float* cr = C + (size_t)(b * TM + t) * N;
#pragma unroll
            for (int nt = 0; nt < 8; nt++) {
#pragma unroll
                for (int j = 0; j < 2; j++) {
                    int n = bn + wn + nt * 8 + tig * 2 + j;
                    cr[n] = acc[mt][nt][i2 * 2 + j] + bias[n];
                }
            }
        }
    }
#undef LDA_CHUNK
#undef LDW_CHUNK
#undef ST_CHUNK
}

// ---------------- tf32 recurrent GEMM body: M=32, n-tile 128, k-chunk 256 ----------------
// At row-major [32][HH] fp32; Wt [k][n] stride H3. Writes slab [b][n] row-major.
__device__ __forceinline__ void rec_mma_body(
    const float* __restrict__ At, const float* __restrict__ Wt,
    float* __restrict__ P,
    uint32_t (*As)[33], uint32_t (*Ws)[132],
    int tid, int n0, int k0) {
    const int warp = tid >> 5, lane = tid & 31;
    const int wn = warp * 16;           // 8 warps x n16
    const int g = lane >> 2, tig = lane & 3;
    const int am = tid >> 3, akq = (tid & 7) * 4;

    float acc[2][2][4];
#pragma unroll
    for (int a = 0; a < 2; a++)
#pragma unroll
        for (int b = 0; b < 2; b++)
#pragma unroll
            for (int c = 0; c < 4; c++) acc[a][b][c] = 0.f;

    float4 pa;
    float4 pw[4];
    pa = ld4(At + (size_t)am * HH + k0 + akq);
#pragma unroll
    for (int i = 0; i < 4; i++) {
        int e = tid + i * 256;
        pw[i] = ld4(Wt + (size_t)(k0 + (e >> 5)) * H3 + n0 + (e & 31) * 4);
    }
    As[akq + 0][am] = f2tf(pa.x); As[akq + 1][am] = f2tf(pa.y);
    As[akq + 2][am] = f2tf(pa.z); As[akq + 3][am] = f2tf(pa.w);
#pragma unroll
    for (int i = 0; i < 4; i++) {
        int e = tid + i * 256;
        uint4 u = make_uint4(f2tf(pw[i].x), f2tf(pw[i].y), f2tf(pw[i].z), f2tf(pw[i].w));
        *reinterpret_cast<uint4*>(&Ws[e >> 5][(e & 31) * 4]) = u;
    }
    __syncthreads();

    for (int c = 0; c < 8; c++) {
        bool has_next = c < 7;
        if (has_next) {
            int kn = k0 + (c + 1) * 32;
            pa = ld4(At + (size_t)am * HH + kn + akq);
#pragma unroll
            for (int i = 0; i < 4; i++) {
                int e = tid + i * 256;
                pw[i] = ld4(Wt + (size_t)(kn + (e >> 5)) * H3 + n0 + (e & 31) * 4);
            }
        }
#pragma unroll
        for (int kk = 0; kk < 32; kk += 8) {
            uint32_t af[2][4];
#pragma unroll
            for (int mt = 0; mt < 2; mt++) {
                int ml = mt * 16 + g;
                af[mt][0] = As[kk + tig][ml];
                af[mt][1] = As[kk + tig][ml + 8];
                af[mt][2] = As[kk + tig + 4][ml];
                af[mt][3] = As[kk + tig + 4][ml + 8];
            }
            uint32_t bf[2][2];
#pragma unroll
            for (int nt = 0; nt < 2; nt++) {
                int nl = wn + nt * 8 + g;
                bf[nt][0] = Ws[kk + tig][nl];
                bf[nt][1] = Ws[kk + tig + 4][nl];
            }
#pragma unroll
            for (int mt = 0; mt < 2; mt++)
#pragma unroll
                for (int nt = 0; nt < 2; nt++) {
                    asm volatile(
                        "mma.sync.aligned.m16n8k8.row.col.f32.tf32.tf32.f32 "
                        "{%0,%1,%2,%3}, {%4,%5,%6,%7}, {%8,%9}, {%0,%1,%2,%3};\n"
                        : "+f"(acc[mt][nt][0]), "+f"(acc[mt][nt][1]),
                          "+f"(acc[mt][nt][2]), "+f"(acc[mt][nt][3])
                        : "r"(af[mt][0]), "r"(af[mt][1]), "r"(af[mt][2]), "r"(af[mt][3]),
                          "r"(bf[nt][0]), "r"(bf[nt][1]));
                }
        }
        __syncthreads();
        if (has_next) {
            As[akq + 0][am] = f2tf(pa.x); As[akq + 1][am] = f2tf(pa.y);
            As[akq + 2][am] = f2tf(pa.z); As[akq + 3][am] = f2tf(pa.w);
#pragma unroll
            for (int i = 0; i < 4; i++) {
                int e = tid + i * 256;
                uint4 u = make_uint4(f2tf(pw[i].x), f2tf(pw[i].y),
                                     f2tf(pw[i].z), f2tf(pw[i].w));
                *reinterpret_cast<uint4*>(&Ws[e >> 5][(e & 31) * 4]) = u;
            }
            __syncthreads();
        }
    }

    // epilogue: acc rows -> slab [b][n]
#pragma unroll
    for (int mt = 0; mt < 2; mt++) {
#pragma unroll
        for (int i2 = 0; i2 < 2; i2++) {
            int b = mt * 16 + g + i2 * 8;
            float* pr = P + (size_t)b * H3 + n0 + wn;
#pragma unroll
            for (int nt = 0; nt < 2; nt++) {
#pragma unroll
                for (int j = 0; j < 2; j++)
                    pr[nt * 8 + tig * 2 + j] = acc[mt][nt][i2 * 2 + j];
            }
        }
    }
}

// encoder wavefront rec: z0 h0@ewhh0 (slabs0-3), z1 h0@ewih1 (4-7), z2 h1@ewhh1 (8-11)
__global__ void __launch_bounds__(256)
enc_rec(const float* __restrict__ h0c, const float* __restrict__ h1c,
        const float* __restrict__ wt_whh0, const float* __restrict__ wt_wih1,
        const float* __restrict__ wt_whh1, float* __restrict__ part) {
    __shared__ uint32_t As[32][33];
    __shared__ uint32_t Ws[32][132];
    const int z = blockIdx.z;
    const float* A = (z == 2) ? h1c : h0c;
    const float* W = (z == 0) ? wt_whh0 : (z == 1) ? wt_wih1 : wt_whh1;
    rec_mma_body(A, W, part + (size_t)(z * KSPLIT + blockIdx.y) * PARTSZ,
                 As, Ws, threadIdx.x, blockIdx.x * 128, blockIdx.y * 256);
}

// encoder wavefront gate: blocks 0-127 layer0 (t0), 128-255 layer1 (t1)
__global__ void __launch_bounds__(256)
enc_gate(const float* __restrict__ part,
         const float* __restrict__ gi0,      // [t][b][n]
         const float* __restrict__ bhh0, const float* __restrict__ bih1,
         const float* __restrict__ bhh1,
         const float* __restrict__ h0c, float* __restrict__ h0n,
         const float* __restrict__ h1c, float* __restrict__ h1n,
         float* __restrict__ encout,
         int t0, int t0v, int t1, int t1v) {
    const int lay = blockIdx.x >> 7;
    const int lb = blockIdx.x & 127;
    const int b = lb >> 2;
    const int h = (lb & 3) * 256 + threadIdx.x;
    if (lay == 0) {
        if (!t0v) return;
        const float* G = gi0 + ((size_t)t0 * BB + b) * H3;
        float gr = G[h], gz = G[HH + h], gn = G[2 * HH + h];
        float hr = bhh0[h], hz = bhh0[HH + h], hn = bhh0[2 * HH + h];
#pragma unroll
        for (int j = 0; j < KSPLIT; j++) {
            const float* P = part + (size_t)j * PARTSZ + (size_t)b * H3;
            hr += P[h]; hz += P[HH + h]; hn += P[2 * HH + h];
        }
        float r = 1.f / (1.f + expf(-(gr + hr)));
        float z = 1.f / (1.f + expf(-(gz + hz)));
        float n = tanhf(gn + r * hn);
        float hp = h0c[(size_t)b * HH + h];
        h0n[(size_t)b * HH + h] = (1.f - z) * n + z * hp;
    } else {
        if (!t1v) return;
        float gr = bih1[h], gz = bih1[HH + h], gn = bih1[2 * HH + h];
        float hr = bhh1[h], hz = bhh1[HH + h], hn = bhh1[2 * HH + h];
#pragma unroll
        for (int j = 0; j < KSPLIT; j++) {
            const float* Px = part + (size_t)(KSPLIT + j) * PARTSZ + (size_t)b * H3;
            const float* Ph = part + (size_t)(2 * KSPLIT + j) * PARTSZ + (size_t)b * H3;
            gr += Px[h]; gz += Px[HH + h]; gn += Px[2 * HH + h];
            hr += Ph[h]; hz += Ph[HH + h]; hn += Ph[2 * HH + h];
        }
        float r = 1.f / (1.f + expf(-(gr + hr)));
        float z = 1.f / (1.f + expf(-(gz + hz)));
        float n = tanhf(gn + r * hn);
        float hp = h1c[(size_t)b * HH + h];
        float out = (1.f - z) * n + z * hp;
        h1n[(size_t)b * HH + h] = out;
        encout[((size_t)b * SS + t1) * HH + h] = out;
    }
}

// decoder launch A: blocks 0-31 attention; 32+: rec z0 h0@dwhh0 (slabs0-3), z1 h1@dwhh1 (4-7)
__global__ void __launch_bounds__(256)
dec_A(const float* __restrict__ proj, const float* __restrict__ d1,
      const int* __restrict__ src_ids, float* __restrict__ attw,
      const float* __restrict__ h0c, const float* __restrict__ h1c,
      const float* __restrict__ wt_whh0, const float* __restrict__ wt_whh1,
      float* __restrict__ part) {
    __shared__ uint32_t As[32][33];
    __shared__ uint32_t Ws[32][132];
    const int bid = blockIdx.x;
    const int tid = threadIdx.x;
    if (bid < 32) {
        float* sc = reinterpret_cast<float*>(Ws);
        const int b = bid;
        const int lane = tid & 31, warp = tid >> 5;
        const float* d1b = d1 + (size_t)b * HH;
        for (int s = warp; s < SS; s += 8) {
            const float* pr = proj + ((size_t)b * SS + s) * HH;
            float p = 0.f;
#pragma unroll
            for (int j = 0; j < 8; j++) {
                int k0 = j * 128 + lane * 4;
                float4 dv = ld4(d1b + k0);
                float4 pv = ld4(pr + k0);
                p += dv.x * pv.x + dv.y * pv.y + dv.z * pv.z + dv.w * pv.w;
            }
#pragma unroll
            for (int o = 16; o; o >>= 1) p += __shfl_xor_sync(0xffffffffu, p, o);
            if (lane == 0) sc[s] = (src_ids[b * SS + s] != 0) ? p : -1e9f;
        }
        __syncthreads();
        if (warp == 0) {
            float v0 = sc[lane], v1 = sc[lane + 32];
            float m = fmaxf(v0, v1);
#pragma unroll
            for (int o = 16; o; o >>= 1) m = fmaxf(m, __shfl_xor_sync(0xffffffffu, m, o));
            float e0 = expf(v0 - m), e1 = expf(v1 - m);
            float su = e0 + e1;
#pragma unroll
            for (int o = 16; o; o >>= 1) su += __shfl_xor_sync(0xffffffffu, su, o);
            attw[b * SS + lane] = e0 / su;
            attw[b * SS + lane + 32] = e1 / su;
        }
    } else {
        const int e = bid - 32;          // 0..191
        const int z = e / 96;            // 0: h0@whh0, 1: h1@whh1
        const int r = e % 96;
        const int n0 = (r % 24) * 128;
        const int kc = r / 24;           // 0..3
        const float* A = z ? h1c : h0c;
        const float* W = z ? wt_whh1 : wt_whh0;
        rec_mma_body(A, W, part + (size_t)(z * KSPLIT + kc) * PARTSZ,
                     As, Ws, tid, n0, kc * 256);
    }
}

// decoder gate0: gi = epre + Σ_s attw*encV ; h-side = slabs 0-3
__global__ void __launch_bounds__(256)
dec_gate0(const float* __restrict__ part,
          const float* __restrict__ epre_t,   // [b][n]
          const float* __restrict__ encV,     // [b][s][n]
          const float* __restrict__ attw,
          const float* __restrict__ bhh0,
          const float* __restrict__ h0c, float* __restrict__ h0n) {
    __shared__ float aw[SS];
    const int b = blockIdx.x >> 2;
    const int h = (blockIdx.x & 3) * 256 + threadIdx.x;
    if (threadIdx.x < SS) aw[threadIdx.x] = attw[b * SS + threadIdx.x];
    __syncthreads();
    const float* G = epre_t + (size_t)b * H3;
    float gr = G[h], gz = G[HH + h], gn = G[2 * HH + h];
    const float* V = encV + (size_t)b * SS * H3;
#pragma unroll 4
    for (int s = 0; s < SS; s++) {
        float w = aw[s];
        const float* vr = V + (size_t)s * H3;
        gr += w * vr[h];
        gz += w * vr[HH + h];
        gn += w * vr[2 * HH + h];
    }
    float hr = bhh0[h], hz = bhh0[HH + h], hn = bhh0[2 * HH + h];
#pragma unroll
    for (int j = 0; j < KSPLIT; j++) {
        const float* P = part + (size_t)j * PARTSZ + (size_t)b * H3;
        hr += P[h]; hz += P[HH + h]; hn += P[2 * HH + h];
    }
    float r = 1.f / (1.f + expf(-(gr + hr)));
    float z = 1.f / (1.f + expf(-(gz + hz)));
    float n = tanhf(gn + r * hn);
    float hp = h0c[(size_t)b * HH + h];
    h0n[(size_t)b * HH + h] = (1.f - z) * n + z * hp;
}

// decoder launch C: rec h0'@dwih1 -> slabs 8-11
__global__ void __launch_bounds__(256)
dec_C(const float* __restrict__ h0n, const float* __restrict__ wt_wih1,
      float* __restrict__ part) {
    __shared__ uint32_t As[32][33];
    __shared__ uint32_t Ws[32][132];
    rec_mma_body(h0n, wt_wih1, part + (size_t)(2 * KSPLIT + blockIdx.y) * PARTSZ,
                 As, Ws, threadIdx.x, blockIdx.x * 128, blockIdx.y * 256);
}

// decoder gate1: x = slabs 8-11 + bih1; h = slabs 4-7 + bhh1; writes h1', cat [d1|ctx]
__global__ void __launch_bounds__(256)
dec_gate1(const float* __restrict__ part,
          const float* __restrict__ bih1, const float* __restrict__ bhh1,
          const float* __restrict__ encout,   // [b][s][h]
          const float* __restrict__ attw,
          const float* __restrict__ h1c, float* __restrict__ h1n,
          float* __restrict__ cat_t) {
    __shared__ float aw[SS];
    const int b = blockIdx.x >> 2;
    const int h = (blockIdx.x & 3) * 256 + threadIdx.x;
    if (threadIdx.x < SS) aw[threadIdx.x] = attw[b * SS + threadIdx.x];
    __syncthreads();
    float gr = bih1[h], gz = bih1[HH + h], gn = bih1[2 * HH + h];
    float hr = bhh1[h], hz = bhh1[HH + h], hn = bhh1[2 * HH + h];
#pragma unroll
    for (int j = 0; j < KSPLIT; j++) {
        const float* Px = part + (size_t)(2 * KSPLIT + j) * PARTSZ + (size_t)b * H3;
        const float* Ph = part + (size_t)(KSPLIT + j) * PARTSZ + (size_t)b * H3;
        gr += Px[h]; gz += Px[HH + h]; gn += Px[2 * HH + h];
        hr += Ph[h]; hz += Ph[HH + h]; hn += Ph[2 * HH + h];
    }
    float r = 1.f / (1.f + expf(-(gr + hr)));
    float z = 1.f / (1.f + expf(-(gz + hz)));
    float n = tanhf(gn + r * hn);
    float hp = h1c[(size_t)b * HH + h];
    float out = (1.f - z) * n + z * hp;
    h1n[(size_t)b * HH + h] = out;
    cat_t[(size_t)b * H2 + h] = out;
    const float* E = encout + (size_t)b * SS * HH;
    float c = 0.f;
#pragma unroll 8
    for (int s = 0; s < SS; s++) c += aw[s] * E[(size_t)s * HH + h];
    cat_t[(size_t)b * H2 + HH + h] = c;
}

// ---------------- host launcher ----------------
extern "C" void kernel_launch(void* const* d_in, const int* in_sizes, int n_in,
                              void* d_out, int out_size) {
    const int*   src_ids  = (const int*)d_in[0];
    const int*   tgt_ids  = (const int*)d_in[2];
    const float* enc_emb  = (const float*)d_in[3];
    const float* dec_emb  = (const float*)d_in[4];
    const float* enc_wih0 = (const float*)d_in[5];
    const float* enc_whh0 = (const float*)d_in[6];
    const float* enc_bih0 = (const float*)d_in[7];
    const float* enc_bhh0 = (const float*)d_in[8];
    const float* enc_wih1 = (const float*)d_in[9];
    const float* enc_whh1 = (const float*)d_in[10];
    const float* enc_bih1 = (const float*)d_in[11];
    const float* enc_bhh1 = (const float*)d_in[12];
    const float* dec_wih0 = (const float*)d_in[13];
    const float* dec_whh0 = (const float*)d_in[14];
    const float* dec_bih0 = (const float*)d_in[15];
    const float* dec_bhh0 = (const float*)d_in[16];
    const float* dec_wih1 = (const float*)d_in[17];
    const float* dec_whh1 = (const float*)d_in[18];
    const float* dec_bih1 = (const float*)d_in[19];
    const float* dec_bhh1 = (const float*)d_in[20];
    const float* attn_w   = (const float*)d_in[21];
    const float* out_w    = (const float*)d_in[22];
    const float* out_b    = (const float*)d_in[23];
    float* out = (float*)d_out;

    float* base = nullptr;
    cudaGetSymbolAddress((void**)&base, g_scratch);
    float* embS   = base + OFF_EMBS;
    float* gi0    = base + OFF_GI0;
    float* encout = base + OFF_ENCOUT;
    float* proj   = base + OFF_PROJ;
    float* encV   = base + OFF_ENCV;
    float* embT   = base + OFF_EMBT;
    float* epre   = base + OFF_EPRE;
    float* cat    = base + OFF_CAT;
    float* h0A    = base + OFF_H0A;
    float* h0B    = base + OFF_H0B;
    float* h1A    = base + OFF_H1A;
    float* h1B    = base + OFF_H1B;
    float* attw   = base + OFF_ATTW;
    float* part   = base + OFF_PART;
    float* wt_ewhh0 = base + OFF_WT + 0 * WT_SZ;
    float* wt_ewhh1 = base + OFF_WT + 1 * WT_SZ;
    float* wt_ewih1 = base + OFF_WT + 2 * WT_SZ;
    float* wt_dwhh0 = base + OFF_WT + 3 * WT_SZ;
    float* wt_dwhh1 = base + OFF_WT + 4 * WT_SZ;
    float* wt_dwih1 = base + OFF_WT + 5 * WT_SZ;

    cudaFuncSetAttribute(gemm_final, cudaFuncAttributeMaxDynamicSharedMemorySize, FSM_BYTES);

    transpose_all<<<dim3(H3 / 32, HH / 32, 6), 256>>>(
        enc_whh0, enc_whh1, enc_wih1, dec_whh0, dec_whh1, dec_wih1, base + OFF_WT);
    embed_enc_kernel<<<(BB * SS * EE + 255) / 256, 256>>>(src_ids, enc_emb, embS);
    embed_dec_kernel<<<(TM * BB * EE + 255) / 256, 256>>>(tgt_ids, dec_emb, embT);
    gemm_tf32<MODE_TENC><<<dim3(H3 / 128, 16), 256>>>(
        embS, EE, enc_wih0, EE, enc_bih0, gi0, BB * SS, H3, EE);
    zero_kernel<<<(4 * BB * HH + 255) / 256, 256>>>(h0A, 4 * BB * HH);
    // epre = embT @ dec_wih0[:, :E]^T + dec_bih0 -> [t][b][n]
    gemm_tf32<MODE_NORM><<<dim3(H3 / 128, (TM * BB + 127) / 128), 256>>>(
        embT, EE, dec_wih0, EE + HH, dec_bih0, epre, TM * BB, H3, EE);

    float* h0_cur = h0A; float* h0_nxt = h0B;
    float* h1_cur = h1A; float* h1_nxt = h1B;

    // ---- encoder wavefront: 65 stages, 2 launches each ----
    for (int s = 0; s <= SS; s++) {
        enc_rec<<<dim3(24, KSPLIT, 3), 256>>>(h0_cur, h1_cur,
                                              wt_ewhh0, wt_ewih1, wt_ewhh1, part);
        enc_gate<<<256, 256>>>(part, gi0, enc_bhh0, enc_bih1, enc_bhh1,
                               h0_cur, h0_nxt, h1_cur, h1_nxt, encout,
                               s, (s < SS) ? 1 : 0, s - 1, (s > 0) ? 1 : 0);
        if (s < SS) { float* tmp = h0_cur; h0_cur = h0_nxt; h0_nxt = tmp; }
        if (s > 0)  { float* tmp = h1_cur; h1_cur = h1_nxt; h1_nxt = tmp; }
    }

    // proj = encout @ attn_w^T ; encV = encout @ dec_wih0[:, E:]^T
    gemm_tf32<MODE_NORM><<<dim3(HH / 128, 16), 256>>>(
        encout, HH, attn_w, HH, nullptr, proj, BB * SS, HH, HH);
    gemm_tf32<MODE_NORM><<<dim3(H3 / 128, 16), 256>>>(
        encout, HH, dec_wih0 + EE, EE + HH, nullptr, encV, BB * SS, H3, HH);

    // ---- decoder loop: 4 launches per step ----
    for (int t = 0; t < TM; t++) {
        float* epre_t = epre + (size_t)t * BB * H3;
        float* cat_t  = cat + (size_t)t * BB * H2;
        dec_A<<<32 + 2 * 96, 256>>>(proj, h1_cur, src_ids, attw,
                                    h0_cur, h1_cur, wt_dwhh0, wt_dwhh1, part);
        dec_gate0<<<128, 256>>>(part, epre_t, encV, attw, dec_bhh0, h0_cur, h0_nxt);
        dec_C<<<dim3(24, KSPLIT), 256>>>(h0_nxt, wt_dwih1, part);
        dec_gate1<<<128, 256>>>(part, dec_bih1, dec_bhh1, encout, attw,
                                h1_cur, h1_nxt, cat_t);
        float* tmp;
        tmp = h0_cur; h0_cur = h0_nxt; h0_nxt = tmp;
        tmp = h1_cur; h1_cur = h1_nxt; h1_nxt = tmp;
    }

    // ---- final projection: logits = cat @ out_w^T + out_b -> (B, TM, V) ----
    gemm_final<<<dim3((TM * BB + 127) / 128, VV / 256), 256, FSM_BYTES>>>(
        cat, H2, out_w, H2, out_b, out, TM * BB, VV, H2);
}